// round 1
// baseline (speedup 1.0000x reference)
#include <cuda_runtime.h>
#include <cstdint>

#define B_ 16
#define C_ 32
#define V_ 512
#define L_ 168
#define VL_ (V_*L_)                      // 86016
#define NELEM ((size_t)B_*C_*V_*L_)      // 44040192
#define ALPHA 0.05f
#define OMA   0.95f

#define BM 128
#define BN 56
#define BK 16

// Scratch (allocation-free rule: __device__ globals)
__device__ float g_P[V_*V_];             // P[w][v] = a_norm[v][w]
__device__ float g_d[V_];
__device__ float g_h[3ULL*44040192ULL];  // h1,h2,h3

// ---------------- adjacency normalization ----------------
__global__ void rowsum_kernel(const float* __restrict__ adj) {
    int v = blockIdx.x;
    float s = 0.f;
    for (int w = threadIdx.x; w < V_; w += blockDim.x) s += adj[v*V_ + w];
    __shared__ float sh[128];
    sh[threadIdx.x] = s;
    __syncthreads();
    for (int off = 64; off > 0; off >>= 1) {
        if (threadIdx.x < off) sh[threadIdx.x] += sh[threadIdx.x + off];
        __syncthreads();
    }
    if (threadIdx.x == 0) g_d[v] = sh[0] + 1.0f;   // +1 from identity on the diagonal
}

__global__ void buildP_kernel(const float* __restrict__ adj) {
    int idx = blockIdx.x * blockDim.x + threadIdx.x;   // idx = w*512 + v
    int w = idx >> 9, v = idx & 511;
    float a = adj[v*V_ + w] + (v == w ? 1.f : 0.f);
    g_P[idx] = a / g_d[v];
}

// ---------------- propagation: dst = ALPHA*x + OMA * P @ src (per b,c) -----
// GEMM per (b,c): D[w,l] = sum_v P[w,v] * src[v,l];  M=512, N=168, K=512
// BM=128 x BN=56 tile, 128 threads (ty 0..15, tx 0..7), 8x7 register tile.
__global__ __launch_bounds__(128, 4) void prop_kernel(const float* __restrict__ xg,
                                                      int src_sel, int dst_sel) {
    const float* __restrict__ src = (src_sel < 0) ? xg : (g_h + (size_t)src_sel * NELEM);
    float* __restrict__ dst = g_h + (size_t)dst_sel * NELEM;

    const int l0 = blockIdx.x * BN;      // 0,56,112
    const int w0 = blockIdx.y * BM;      // 0..384
    const int bc = blockIdx.z;           // 0..511
    const int t  = threadIdx.x;
    const int tx = t & 7;
    const int ty = t >> 3;

    __shared__ float As[2][BK][BM];      // As[k][w] (transposed P tile)
    __shared__ float Bs[2][BK][BN];

    const size_t base = (size_t)bc * VL_;

    float4 a4[4];
    float  b7[7];

    // ---- prologue: fetch + store k-tile 0 into buffer 0
    {
        const int k0 = 0;
        #pragma unroll
        for (int q = 0; q < 4; q++) {
            int j = q * 128 + t;
            int w = j >> 2;
            int co = (j & 3) * 4;
            a4[q] = *(const float4*)&g_P[(size_t)(w0 + w) * V_ + k0 + co];
        }
        #pragma unroll
        for (int i = 0; i < 7; i++) {
            int idx = i * 128 + t;
            int row = idx / BN, col = idx % BN;
            b7[i] = src[base + (size_t)(k0 + row) * L_ + l0 + col];
        }
        #pragma unroll
        for (int q = 0; q < 4; q++) {
            int j = q * 128 + t;
            int w = j >> 2;
            int co = (j & 3) * 4;
            As[0][co+0][w] = a4[q].x;
            As[0][co+1][w] = a4[q].y;
            As[0][co+2][w] = a4[q].z;
            As[0][co+3][w] = a4[q].w;
        }
        #pragma unroll
        for (int i = 0; i < 7; i++) {
            int idx = i * 128 + t;
            Bs[0][idx / BN][idx % BN] = b7[i];
        }
    }
    __syncthreads();

    float acc[8][7];
    #pragma unroll
    for (int i = 0; i < 8; i++)
        #pragma unroll
        for (int j = 0; j < 7; j++) acc[i][j] = 0.f;

    const int NKT = V_ / BK;   // 32
    for (int kt = 0; kt < NKT; kt++) {
        const int cur = kt & 1;
        // fetch next tile into registers (LDG overlaps with compute)
        if (kt < NKT - 1) {
            const int k0 = (kt + 1) * BK;
            #pragma unroll
            for (int q = 0; q < 4; q++) {
                int j = q * 128 + t;
                int w = j >> 2;
                int co = (j & 3) * 4;
                a4[q] = *(const float4*)&g_P[(size_t)(w0 + w) * V_ + k0 + co];
            }
            #pragma unroll
            for (int i = 0; i < 7; i++) {
                int idx = i * 128 + t;
                int row = idx / BN, col = idx % BN;
                b7[i] = src[base + (size_t)(k0 + row) * L_ + l0 + col];
            }
        }
        // compute from current smem buffer
        #pragma unroll
        for (int kk = 0; kk < BK; kk++) {
            float ar[8], br[7];
            float4 av0 = *(const float4*)&As[cur][kk][ty*8 + 0];
            float4 av1 = *(const float4*)&As[cur][kk][ty*8 + 4];
            ar[0]=av0.x; ar[1]=av0.y; ar[2]=av0.z; ar[3]=av0.w;
            ar[4]=av1.x; ar[5]=av1.y; ar[6]=av1.z; ar[7]=av1.w;
            #pragma unroll
            for (int j = 0; j < 7; j++) br[j] = Bs[cur][kk][tx + j*8];
            #pragma unroll
            for (int i = 0; i < 8; i++)
                #pragma unroll
                for (int j = 0; j < 7; j++)
                    acc[i][j] += ar[i] * br[j];
        }
        // stage next tile into the other buffer
        if (kt < NKT - 1) {
            const int nb = cur ^ 1;
            #pragma unroll
            for (int q = 0; q < 4; q++) {
                int j = q * 128 + t;
                int w = j >> 2;
                int co = (j & 3) * 4;
                As[nb][co+0][w] = a4[q].x;
                As[nb][co+1][w] = a4[q].y;
                As[nb][co+2][w] = a4[q].z;
                As[nb][co+3][w] = a4[q].w;
            }
            #pragma unroll
            for (int i = 0; i < 7; i++) {
                int idx = i * 128 + t;
                Bs[nb][idx / BN][idx % BN] = b7[i];
            }
        }
        __syncthreads();
    }

    // epilogue: dst = ALPHA*x + OMA*acc   (no bounds checks: exact tiling)
    #pragma unroll
    for (int i = 0; i < 8; i++) {
        const size_t roff = base + (size_t)(w0 + ty*8 + i) * L_ + l0;
        #pragma unroll
        for (int j = 0; j < 7; j++) {
            int l = tx + j*8;
            dst[roff + l] = ALPHA * xg[roff + l] + OMA * acc[i][j];
        }
    }
}

// ---------------- final channel mix: out = bias + W @ concat(x,h1,h2,h3) ----
// One thread: one (b, vl-quad), 16 of 32 output channels (blockIdx.y selects half)
__global__ __launch_bounds__(256) void mix_kernel(const float* __restrict__ x,
                                                  const float* __restrict__ W,
                                                  const float* __restrict__ bias,
                                                  float* __restrict__ out) {
    __shared__ float Ws[16][128];
    const int oo = blockIdx.y * 16;
    for (int i = threadIdx.x; i < 16*128; i += 256)
        Ws[i >> 7][i & 127] = W[oo*128 + i];
    __syncthreads();

    const int VL4 = VL_ / 4;                   // 21504
    int gid = blockIdx.x * 256 + threadIdx.x;  // 0..344063
    int b = gid / VL4;
    int pos = (gid - b * VL4) * 4;

    float4 acc[16];
    #pragma unroll
    for (int o = 0; o < 16; o++) {
        float bv = bias[oo + o];
        acc[o] = make_float4(bv, bv, bv, bv);
    }

    const size_t boff = (size_t)b * C_ * VL_ + (size_t)pos;
    const float* srcs[4] = { x + boff,
                             g_h + boff,
                             g_h + NELEM + boff,
                             g_h + 2*NELEM + boff };

    #pragma unroll
    for (int k = 0; k < 4; k++) {
        const float* hp = srcs[k];
        #pragma unroll
        for (int c = 0; c < 32; c++) {
            float4 hv = *(const float4*)(hp + (size_t)c * VL_);
            #pragma unroll
            for (int o = 0; o < 16; o++) {
                float wv = Ws[o][k*32 + c];
                acc[o].x += wv * hv.x;
                acc[o].y += wv * hv.y;
                acc[o].z += wv * hv.z;
                acc[o].w += wv * hv.w;
            }
        }
    }

    float* op = out + (size_t)b * C_ * VL_ + (size_t)oo * VL_ + (size_t)pos;
    #pragma unroll
    for (int o = 0; o < 16; o++)
        *(float4*)(op + (size_t)o * VL_) = acc[o];
}

extern "C" void kernel_launch(void* const* d_in, const int* in_sizes, int n_in,
                              void* d_out, int out_size) {
    (void)in_sizes; (void)n_in; (void)out_size;
    const float* x    = (const float*)d_in[0];
    const float* adj  = (const float*)d_in[1];
    const float* W    = (const float*)d_in[2];
    const float* bias = (const float*)d_in[3];
    float* out = (float*)d_out;

    rowsum_kernel<<<V_, 128>>>(adj);
    buildP_kernel<<<(V_*V_)/256, 256>>>(adj);

    dim3 pgrid(L_/BN, V_/BM, B_*C_);   // (3, 4, 512)
    prop_kernel<<<pgrid, 128>>>(x, -1, 0);   // h1 = f(x)
    prop_kernel<<<pgrid, 128>>>(x,  0, 1);   // h2 = f(h1)
    prop_kernel<<<pgrid, 128>>>(x,  1, 2);   // h3 = f(h2)

    mix_kernel<<<dim3((B_*VL_/4)/256, 2), 256>>>(x, W, bias, out);
}

// round 2
// speedup vs baseline: 1.4897x; 1.4897x over previous
#include <cuda_runtime.h>
#include <cuda_bf16.h>
#include <cstdint>

#define B_ 16
#define C_ 32
#define V_ 512
#define L_ 168
#define VL_ (V_*L_)                      // 86016
#define NELEM ((size_t)B_*C_*V_*L_)      // 44040192
#define ALPHA 0.05f
#define OMA   0.95f

// ---------------- device scratch (allocation-free rule) ----------------
__device__ float g_d[V_];
__device__ __nv_bfloat16 g_Phi[V_*V_];   // P[w][v] hi part
__device__ __nv_bfloat16 g_Plo[V_*V_];   // P[w][v] lo part
__device__ __nv_bfloat16 g_xhi[NELEM];
__device__ __nv_bfloat16 g_xlo[NELEM];
__device__ __nv_bfloat16 g_hhi[2*NELEM]; // splits of h1,h2 (h3 not re-propagated)
__device__ __nv_bfloat16 g_hlo[2*NELEM];
__device__ float g_h[3*NELEM];           // fp32 h1,h2,h3 for the final mix

// ---------------- PTX helpers ----------------
__device__ __forceinline__ void cpasync16(uint32_t dst, const void* src) {
    asm volatile("cp.async.cg.shared.global [%0],[%1],16;\n" :: "r"(dst), "l"(src));
}
__device__ __forceinline__ void cpcommit() { asm volatile("cp.async.commit_group;\n"); }
template<int N> __device__ __forceinline__ void cpwait() {
    asm volatile("cp.async.wait_group %0;\n" :: "n"(N));
}
__device__ __forceinline__ void ldsm_x4(uint32_t a[4], uint32_t addr) {
    asm volatile("ldmatrix.sync.aligned.m8n8.x4.shared.b16 {%0,%1,%2,%3},[%4];"
        : "=r"(a[0]), "=r"(a[1]), "=r"(a[2]), "=r"(a[3]) : "r"(addr));
}
__device__ __forceinline__ void ldsm_x2t(uint32_t b[2], uint32_t addr) {
    asm volatile("ldmatrix.sync.aligned.m8n8.x2.trans.shared.b16 {%0,%1},[%2];"
        : "=r"(b[0]), "=r"(b[1]) : "r"(addr));
}
__device__ __forceinline__ void mma16816(float c[4], const uint32_t a[4], const uint32_t b[2]) {
    asm volatile("mma.sync.aligned.m16n8k16.row.col.f32.bf16.bf16.f32 "
        "{%0,%1,%2,%3},{%4,%5,%6,%7},{%8,%9},{%0,%1,%2,%3};"
        : "+f"(c[0]), "+f"(c[1]), "+f"(c[2]), "+f"(c[3])
        : "r"(a[0]), "r"(a[1]), "r"(a[2]), "r"(a[3]), "r"(b[0]), "r"(b[1]));
}

// ---------------- adjacency prep ----------------
__global__ void rowsum_kernel(const float* __restrict__ adj) {
    int v = blockIdx.x;
    float s = 0.f;
    for (int w = threadIdx.x; w < V_; w += blockDim.x) s += adj[v*V_ + w];
    __shared__ float sh[128];
    sh[threadIdx.x] = s;
    __syncthreads();
    for (int off = 64; off > 0; off >>= 1) {
        if (threadIdx.x < off) sh[threadIdx.x] += sh[threadIdx.x + off];
        __syncthreads();
    }
    if (threadIdx.x == 0) g_d[v] = sh[0] + 1.0f;
}

__global__ void buildP_kernel(const float* __restrict__ adj) {
    int idx = blockIdx.x * blockDim.x + threadIdx.x;   // idx = w*512 + v
    int w = idx >> 9, v = idx & 511;
    float a = adj[v*V_ + w] + (v == w ? 1.f : 0.f);
    float p = a / g_d[v];
    __nv_bfloat16 hi = __float2bfloat16_rn(p);
    g_Phi[idx] = hi;
    g_Plo[idx] = __float2bfloat16_rn(p - __bfloat162float(hi));
}

__global__ void split_kernel(const float* __restrict__ x) {
    size_t i = ((size_t)blockIdx.x * 256 + threadIdx.x) * 4;
    float4 v = *(const float4*)(x + i);
    __nv_bfloat16 h0 = __float2bfloat16_rn(v.x), h1 = __float2bfloat16_rn(v.y);
    __nv_bfloat16 h2 = __float2bfloat16_rn(v.z), h3 = __float2bfloat16_rn(v.w);
    *(__nv_bfloat162*)(g_xhi + i)     = __halves2bfloat162(h0, h1);
    *(__nv_bfloat162*)(g_xhi + i + 2) = __halves2bfloat162(h2, h3);
    *(__nv_bfloat162*)(g_xlo + i)     = __halves2bfloat162(
        __float2bfloat16_rn(v.x - __bfloat162float(h0)),
        __float2bfloat16_rn(v.y - __bfloat162float(h1)));
    *(__nv_bfloat162*)(g_xlo + i + 2) = __halves2bfloat162(
        __float2bfloat16_rn(v.z - __bfloat162float(h2)),
        __float2bfloat16_rn(v.w - __bfloat162float(h3)));
}

// ---------------- tensor-core propagation ----------------
// D[w,l] = Phi·Shi + Phi·Slo + Plo·Shi (per bc), dst = ALPHA*x + OMA*D
// block: 128 thr = 4 warps, tile BM=128 x BN=56, BK=32, warp tile 32x56.
// smem stage layout (bytes): Ahi[128][40el], Alo[128][40el], Bhi[32][56el], Blo[32][56el]
#define A_ST   80      // A row stride bytes (40 bf16, bank-conflict-free for ldmatrix)
#define A_TERM 10240   // 128*80
#define B_OFF  20480
#define B_ROW  112     // 56 bf16
#define B_TERM 3584    // 32*112
#define STAGE  27648

__global__ __launch_bounds__(128) void prop_mma(const float* __restrict__ xg,
                                                int src_sel, int dst_sel) {
    extern __shared__ char smem[];
    uint32_t sb = (uint32_t)__cvta_generic_to_shared(smem);
    const int t = threadIdx.x;
    const int warp = t >> 5, lane = t & 31;
    const int l0 = blockIdx.x * 56;
    const int w0 = blockIdx.y * 128;
    const int bc = blockIdx.z;
    const size_t base = (size_t)bc * VL_;

    const __nv_bfloat16* __restrict__ shi =
        (src_sel < 0) ? g_xhi : (g_hhi + (size_t)src_sel * NELEM);
    const __nv_bfloat16* __restrict__ slo =
        (src_sel < 0) ? g_xlo : (g_hlo + (size_t)src_sel * NELEM);
    float* __restrict__ dst = g_h + (size_t)dst_sel * NELEM;
    const bool wr_split = (dst_sel < 2);
    __nv_bfloat16* __restrict__ dhi = g_hhi + (size_t)dst_sel * NELEM;
    __nv_bfloat16* __restrict__ dlo = g_hlo + (size_t)dst_sel * NELEM;

    const __nv_bfloat16* pArow = g_Phi + (size_t)(w0 + t) * V_;
    const __nv_bfloat16* pLrow = g_Plo + (size_t)(w0 + t) * V_;

    auto issue = [&](int s, int kt) {
        uint32_t st = sb + s * STAGE;
        const __nv_bfloat16* pa = pArow + kt * 32;
        const __nv_bfloat16* pl = pLrow + kt * 32;
        #pragma unroll
        for (int q = 0; q < 4; q++) {
            cpasync16(st + t * A_ST + q * 16, pa + q * 8);
            cpasync16(st + A_TERM + t * A_ST + q * 16, pl + q * 8);
        }
        #pragma unroll
        for (int i = 0; i < 4; i++) {
            int idx = i * 128 + t;            // 0..511, need 448
            if (idx < 448) {
                int term = idx / 224;
                int rem = idx - term * 224;
                int row = rem / 7;
                int c = rem - row * 7;
                const __nv_bfloat16* src = (term ? slo : shi) + base
                    + (size_t)(kt * 32 + row) * L_ + l0 + c * 8;
                cpasync16(st + B_OFF + term * B_TERM + row * B_ROW + c * 16, src);
            }
        }
        cpcommit();
    };

    float acc[2][7][4];
    #pragma unroll
    for (int i = 0; i < 2; i++)
        #pragma unroll
        for (int j = 0; j < 7; j++)
            #pragma unroll
            for (int q = 0; q < 4; q++) acc[i][j][q] = 0.f;

    issue(0, 0);
    for (int kt = 0; kt < 16; kt++) {
        if (kt < 15) { issue((kt + 1) & 1, kt + 1); cpwait<1>(); }
        else         { cpwait<0>(); }
        __syncthreads();
        uint32_t st = sb + (kt & 1) * STAGE;
        #pragma unroll
        for (int ks = 0; ks < 2; ks++) {
            uint32_t ah[2][4], al[2][4];
            #pragma unroll
            for (int i = 0; i < 2; i++) {
                int rowA = warp * 32 + i * 16 + (lane & 15);
                uint32_t off = rowA * A_ST + ks * 32 + (lane >> 4) * 16;
                ldsm_x4(ah[i], st + off);
                ldsm_x4(al[i], st + A_TERM + off);
            }
            int rowB = ks * 16 + (lane & 15);
            #pragma unroll
            for (int j = 0; j < 7; j++) {
                uint32_t boff = st + B_OFF + rowB * B_ROW + j * 16;
                uint32_t bh[2], bl[2];
                ldsm_x2t(bh, boff);
                ldsm_x2t(bl, boff + B_TERM);
                #pragma unroll
                for (int i = 0; i < 2; i++) {
                    mma16816(acc[i][j], ah[i], bh);
                    mma16816(acc[i][j], ah[i], bl);
                    mma16816(acc[i][j], al[i], bh);
                }
            }
        }
        __syncthreads();
    }

    // epilogue: dst = ALPHA*x + OMA*acc, plus bf16 hi/lo for the next prop
    const int gr = lane >> 2, gc = (lane & 3) * 2;
    #pragma unroll
    for (int i = 0; i < 2; i++) {
        #pragma unroll
        for (int j = 0; j < 7; j++) {
            #pragma unroll
            for (int h = 0; h < 2; h++) {
                int wrow = w0 + warp * 32 + i * 16 + gr + h * 8;
                int lcol = l0 + j * 8 + gc;
                size_t off = base + (size_t)wrow * L_ + lcol;
                float2 xv = *(const float2*)(xg + off);
                float o0 = ALPHA * xv.x + OMA * acc[i][j][2*h + 0];
                float o1 = ALPHA * xv.y + OMA * acc[i][j][2*h + 1];
                *(float2*)(dst + off) = make_float2(o0, o1);
                if (wr_split) {
                    __nv_bfloat16 b0 = __float2bfloat16_rn(o0);
                    __nv_bfloat16 b1 = __float2bfloat16_rn(o1);
                    *(__nv_bfloat162*)(dhi + off) = __halves2bfloat162(b0, b1);
                    *(__nv_bfloat162*)(dlo + off) = __halves2bfloat162(
                        __float2bfloat16_rn(o0 - __bfloat162float(b0)),
                        __float2bfloat16_rn(o1 - __bfloat162float(b1)));
                }
            }
        }
    }
}

// ---------------- final channel mix (unchanged from R1) ----------------
__global__ __launch_bounds__(256) void mix_kernel(const float* __restrict__ x,
                                                  const float* __restrict__ W,
                                                  const float* __restrict__ bias,
                                                  float* __restrict__ out) {
    __shared__ float Ws[16][128];
    const int oo = blockIdx.y * 16;
    for (int i = threadIdx.x; i < 16*128; i += 256)
        Ws[i >> 7][i & 127] = W[oo*128 + i];
    __syncthreads();

    const int VL4 = VL_ / 4;
    int gid = blockIdx.x * 256 + threadIdx.x;
    int b = gid / VL4;
    int pos = (gid - b * VL4) * 4;

    float4 acc[16];
    #pragma unroll
    for (int o = 0; o < 16; o++) {
        float bv = bias[oo + o];
        acc[o] = make_float4(bv, bv, bv, bv);
    }

    const size_t boff = (size_t)b * C_ * VL_ + (size_t)pos;
    const float* srcs[4] = { x + boff,
                             g_h + boff,
                             g_h + NELEM + boff,
                             g_h + 2*NELEM + boff };

    #pragma unroll
    for (int k = 0; k < 4; k++) {
        const float* hp = srcs[k];
        #pragma unroll
        for (int c = 0; c < 32; c++) {
            float4 hv = *(const float4*)(hp + (size_t)c * VL_);
            #pragma unroll
            for (int o = 0; o < 16; o++) {
                float wv = Ws[o][k*32 + c];
                acc[o].x += wv * hv.x;
                acc[o].y += wv * hv.y;
                acc[o].z += wv * hv.z;
                acc[o].w += wv * hv.w;
            }
        }
    }

    float* op = out + (size_t)b * C_ * VL_ + (size_t)oo * VL_ + (size_t)pos;
    #pragma unroll
    for (int o = 0; o < 16; o++)
        *(float4*)(op + (size_t)o * VL_) = acc[o];
}

extern "C" void kernel_launch(void* const* d_in, const int* in_sizes, int n_in,
                              void* d_out, int out_size) {
    (void)in_sizes; (void)n_in; (void)out_size;
    const float* x    = (const float*)d_in[0];
    const float* adj  = (const float*)d_in[1];
    const float* W    = (const float*)d_in[2];
    const float* bias = (const float*)d_in[3];
    float* out = (float*)d_out;

    cudaFuncSetAttribute(prop_mma, cudaFuncAttributeMaxDynamicSharedMemorySize,
                         2 * STAGE);

    rowsum_kernel<<<V_, 128>>>(adj);
    buildP_kernel<<<(V_*V_)/256, 256>>>(adj);
    split_kernel<<<(int)(NELEM/4/256), 256>>>(x);

    dim3 pgrid(L_/56, V_/128, B_*C_);   // (3, 4, 512)
    prop_mma<<<pgrid, 128, 2*STAGE>>>(x, -1, 0);   // h1 = f(x)
    prop_mma<<<pgrid, 128, 2*STAGE>>>(x,  0, 1);   // h2 = f(h1)
    prop_mma<<<pgrid, 128, 2*STAGE>>>(x,  1, 2);   // h3 = f(h2)

    mix_kernel<<<dim3((B_*VL_/4)/256, 2), 256>>>(x, W, bias, out);
}

// round 3
// speedup vs baseline: 2.7503x; 1.8462x over previous
#include <cuda_runtime.h>
#include <cuda_bf16.h>
#include <cstdint>

#define B_ 16
#define C_ 32
#define V_ 512
#define L_ 168
#define VL_ (V_*L_)                      // 86016
#define CVL_ (C_*VL_)                    // 2752512
#define NELEM ((size_t)B_*C_*V_*L_)      // 44040192
#define ALPHA 0.05f
#define OMA   0.95f

// ---------------- device scratch ----------------
__device__ float g_d[V_];
__device__ __nv_bfloat16 g_Phi[V_*V_];
__device__ __nv_bfloat16 g_Plo[V_*V_];
__device__ __nv_bfloat16 g_xhi[NELEM];
__device__ __nv_bfloat16 g_xlo[NELEM];
__device__ __nv_bfloat16 g_hhi[3*NELEM];
__device__ __nv_bfloat16 g_hlo[3*NELEM];

// ---------------- PTX helpers ----------------
__device__ __forceinline__ void cpasync16(uint32_t dst, const void* src) {
    asm volatile("cp.async.cg.shared.global [%0],[%1],16;\n" :: "r"(dst), "l"(src));
}
__device__ __forceinline__ void cpcommit() { asm volatile("cp.async.commit_group;\n"); }
template<int N> __device__ __forceinline__ void cpwait() {
    asm volatile("cp.async.wait_group %0;\n" :: "n"(N));
}
__device__ __forceinline__ void ldsm_x4(uint32_t a[4], uint32_t addr) {
    asm volatile("ldmatrix.sync.aligned.m8n8.x4.shared.b16 {%0,%1,%2,%3},[%4];"
        : "=r"(a[0]), "=r"(a[1]), "=r"(a[2]), "=r"(a[3]) : "r"(addr));
}
__device__ __forceinline__ void ldsm_x2t(uint32_t b[2], uint32_t addr) {
    asm volatile("ldmatrix.sync.aligned.m8n8.x2.trans.shared.b16 {%0,%1},[%2];"
        : "=r"(b[0]), "=r"(b[1]) : "r"(addr));
}
__device__ __forceinline__ void mma16816(float c[4], const uint32_t a[4], const uint32_t b[2]) {
    asm volatile("mma.sync.aligned.m16n8k16.row.col.f32.bf16.bf16.f32 "
        "{%0,%1,%2,%3},{%4,%5,%6,%7},{%8,%9},{%0,%1,%2,%3};"
        : "+f"(c[0]), "+f"(c[1]), "+f"(c[2]), "+f"(c[3])
        : "r"(a[0]), "r"(a[1]), "r"(a[2]), "r"(a[3]), "r"(b[0]), "r"(b[1]));
}

// ---------------- adjacency prep ----------------
__global__ void rowsum_kernel(const float* __restrict__ adj) {
    int v = blockIdx.x;
    float s = 0.f;
    for (int w = threadIdx.x; w < V_; w += blockDim.x) s += adj[v*V_ + w];
    __shared__ float sh[128];
    sh[threadIdx.x] = s;
    __syncthreads();
    for (int off = 64; off > 0; off >>= 1) {
        if (threadIdx.x < off) sh[threadIdx.x] += sh[threadIdx.x + off];
        __syncthreads();
    }
    if (threadIdx.x == 0) g_d[v] = sh[0] + 1.0f;
}

__global__ void buildP_kernel(const float* __restrict__ adj) {
    int idx = blockIdx.x * blockDim.x + threadIdx.x;   // idx = w*512 + v
    int w = idx >> 9, v = idx & 511;
    float a = adj[v*V_ + w] + (v == w ? 1.f : 0.f);
    float p = a / g_d[v];
    __nv_bfloat16 hi = __float2bfloat16_rn(p);
    g_Phi[idx] = hi;
    g_Plo[idx] = __float2bfloat16_rn(p - __bfloat162float(hi));
}

__global__ void split_kernel(const float* __restrict__ x) {
    size_t i = ((size_t)blockIdx.x * 256 + threadIdx.x) * 4;
    float4 v = *(const float4*)(x + i);
    __nv_bfloat16 h0 = __float2bfloat16_rn(v.x), h1 = __float2bfloat16_rn(v.y);
    __nv_bfloat16 h2 = __float2bfloat16_rn(v.z), h3 = __float2bfloat16_rn(v.w);
    *(__nv_bfloat162*)(g_xhi + i)     = __halves2bfloat162(h0, h1);
    *(__nv_bfloat162*)(g_xhi + i + 2) = __halves2bfloat162(h2, h3);
    *(__nv_bfloat162*)(g_xlo + i)     = __halves2bfloat162(
        __float2bfloat16_rn(v.x - __bfloat162float(h0)),
        __float2bfloat16_rn(v.y - __bfloat162float(h1)));
    *(__nv_bfloat162*)(g_xlo + i + 2) = __halves2bfloat162(
        __float2bfloat16_rn(v.z - __bfloat162float(h2)),
        __float2bfloat16_rn(v.w - __bfloat162float(h3)));
}

// ---------------- tensor-core propagation ----------------
// tile BM=128 x BN=168 (full L), BK=32, 384 threads = 12 warps (4m x 3n),
// warp tile 32x56.  D = Phi*Shi + Phi*Slo + Plo*Shi; out = ALPHA*x + OMA*D,
// written only as bf16 hi/lo split.
#define A_ST   80
#define A_TERM 10240
#define B_OFF  20480   // 2*A_TERM
#define B_ROW  336     // 168 bf16
#define B_TERM 10752   // 32*336
#define STAGE  41984   // B_OFF + 2*B_TERM

__global__ __launch_bounds__(384, 1) void prop_mma(const float* __restrict__ xg,
                                                   int src_sel, int dst_sel) {
    extern __shared__ char smem[];
    uint32_t sb = (uint32_t)__cvta_generic_to_shared(smem);
    const int t = threadIdx.x;
    const int warp = t >> 5, lane = t & 31;
    const int warp_m = warp & 3, warp_n = warp >> 2;     // 4 x 3
    const int w0 = blockIdx.x * 128;
    const int bc = blockIdx.y;
    const size_t base = (size_t)bc * VL_;

    const __nv_bfloat16* __restrict__ shi =
        (src_sel < 0) ? g_xhi : (g_hhi + (size_t)src_sel * NELEM);
    const __nv_bfloat16* __restrict__ slo =
        (src_sel < 0) ? g_xlo : (g_hlo + (size_t)src_sel * NELEM);
    __nv_bfloat16* __restrict__ dhi = g_hhi + (size_t)dst_sel * NELEM;
    __nv_bfloat16* __restrict__ dlo = g_hlo + (size_t)dst_sel * NELEM;

    auto issue = [&](int s, int kt) {
        uint32_t st = sb + s * STAGE;
        #pragma unroll
        for (int i = 0; i < 3; i++) {                 // A: 1024 16B chunks
            int c = i * 384 + t;
            if (c < 1024) {
                int term = c >> 9, rem = c & 511;
                int row = rem >> 2, q = rem & 3;
                const __nv_bfloat16* src = (term ? g_Plo : g_Phi)
                    + (size_t)(w0 + row) * V_ + kt * 32 + q * 8;
                cpasync16(st + term * A_TERM + row * A_ST + q * 16, src);
            }
        }
        #pragma unroll
        for (int i = 0; i < 4; i++) {                 // B: 1344 16B chunks
            int c = i * 384 + t;
            if (c < 1344) {
                int term = c / 672, rem = c - term * 672;
                int row = rem / 21, cc = rem - row * 21;
                const __nv_bfloat16* src = (term ? slo : shi) + base
                    + (size_t)(kt * 32 + row) * L_ + cc * 8;
                cpasync16(st + B_OFF + term * B_TERM + row * B_ROW + cc * 16, src);
            }
        }
        cpcommit();
    };

    float acc[2][7][4];
    #pragma unroll
    for (int i = 0; i < 2; i++)
        #pragma unroll
        for (int j = 0; j < 7; j++)
            #pragma unroll
            for (int q = 0; q < 4; q++) acc[i][j][q] = 0.f;

    issue(0, 0);
    for (int kt = 0; kt < 16; kt++) {
        if (kt < 15) { issue((kt + 1) & 1, kt + 1); cpwait<1>(); }
        else         { cpwait<0>(); }
        __syncthreads();
        uint32_t st = sb + (kt & 1) * STAGE;
        #pragma unroll
        for (int ks = 0; ks < 2; ks++) {
            uint32_t ah[2][4], al[2][4];
            #pragma unroll
            for (int i = 0; i < 2; i++) {
                int rowA = warp_m * 32 + i * 16 + (lane & 15);
                uint32_t off = rowA * A_ST + ks * 32 + (lane >> 4) * 16;
                ldsm_x4(ah[i], st + off);
                ldsm_x4(al[i], st + A_TERM + off);
            }
            int rowB = ks * 16 + (lane & 15);
            #pragma unroll
            for (int j = 0; j < 7; j++) {
                uint32_t boff = st + B_OFF + rowB * B_ROW + warp_n * 112 + j * 16;
                uint32_t bh[2], bl[2];
                ldsm_x2t(bh, boff);
                ldsm_x2t(bl, boff + B_TERM);
                #pragma unroll
                for (int i = 0; i < 2; i++) {
                    mma16816(acc[i][j], ah[i], bh);
                    mma16816(acc[i][j], ah[i], bl);
                    mma16816(acc[i][j], al[i], bh);
                }
            }
        }
        __syncthreads();
    }

    // epilogue: o = ALPHA*x + OMA*acc -> bf16 hi/lo split only
    const int gr = lane >> 2, gc = (lane & 3) * 2;
    #pragma unroll
    for (int i = 0; i < 2; i++) {
        #pragma unroll
        for (int j = 0; j < 7; j++) {
            #pragma unroll
            for (int h = 0; h < 2; h++) {
                int wrow = w0 + warp_m * 32 + i * 16 + gr + h * 8;
                int lcol = warp_n * 56 + j * 8 + gc;
                size_t off = base + (size_t)wrow * L_ + lcol;
                float2 xv = *(const float2*)(xg + off);
                float o0 = ALPHA * xv.x + OMA * acc[i][j][2*h + 0];
                float o1 = ALPHA * xv.y + OMA * acc[i][j][2*h + 1];
                __nv_bfloat16 b0 = __float2bfloat16_rn(o0);
                __nv_bfloat16 b1 = __float2bfloat16_rn(o1);
                *(__nv_bfloat162*)(dhi + off) = __halves2bfloat162(b0, b1);
                *(__nv_bfloat162*)(dlo + off) = __halves2bfloat162(
                    __float2bfloat16_rn(o0 - __bfloat162float(b0)),
                    __float2bfloat16_rn(o1 - __bfloat162float(b1)));
            }
        }
    }
}

// ---------------- tensor-core channel mix ----------------
// out[o, b*VL+p] = bias[o] + W[o,0:128] . feat[0:128, p]
// feat rows: 0-31 x, 32-63 h1, 64-95 h2, 96-127 h3 (each as hi/lo bf16 pair)
// M=32, K=128, per-block N tile = 128. 128 thr = 4 warps along N (32 cols each).
#define MROW 272      // padded row stride bytes (128 bf16 = 256B + 16 pad)
#define MTERM 8704    // 32*272
#define WBYTES 17408  // 2 terms of W
#define MSTAGE 17408  // 2 terms of B
#define MIX_SMEM (WBYTES + 2*MSTAGE)   // 52224

__global__ __launch_bounds__(128) void mix_mma(const float* __restrict__ Wg,
                                               const float* __restrict__ bias,
                                               float* __restrict__ out) {
    extern __shared__ char smem[];
    uint32_t sb = (uint32_t)__cvta_generic_to_shared(smem);
    const int t = threadIdx.x;
    const int warp = t >> 5, lane = t & 31;
    const int n0 = blockIdx.x * 128;       // position within (v,l) plane
    const int b = blockIdx.y;
    const size_t boff = (size_t)b * CVL_;

    // W split -> smem (hi at 0, lo at MTERM)
    #pragma unroll
    for (int i = 0; i < 32; i++) {
        int idx = i * 128 + t;             // 4096 total
        int o = idx >> 7, ch = idx & 127;
        float w = Wg[idx];
        __nv_bfloat16 hi = __float2bfloat16_rn(w);
        __nv_bfloat16 lo = __float2bfloat16_rn(w - __bfloat162float(hi));
        *(__nv_bfloat16*)(smem + o * MROW + ch * 2) = hi;
        *(__nv_bfloat16*)(smem + MTERM + o * MROW + ch * 2) = lo;
    }

    const __nv_bfloat16* hitbl[4] = { g_xhi + boff, g_hhi + boff,
                                      g_hhi + NELEM + boff, g_hhi + 2*NELEM + boff };
    const __nv_bfloat16* lotbl[4] = { g_xlo + boff, g_hlo + boff,
                                      g_hlo + NELEM + boff, g_hlo + 2*NELEM + boff };

    auto issue = [&](int s, int kt) {
        uint32_t st = sb + WBYTES + s * MSTAGE;
        #pragma unroll
        for (int i = 0; i < 8; i++) {                  // 1024 chunks exactly
            int c = i * 128 + t;
            int term = c >> 9, rem = c & 511;
            int row = rem >> 4, cc = rem & 15;         // row = channel-in-slot
            const __nv_bfloat16* src = (term ? lotbl[kt] : hitbl[kt])
                + (size_t)row * VL_ + n0 + cc * 8;
            cpasync16(st + term * MTERM + row * MROW + cc * 16, src);
        }
        cpcommit();
    };

    float acc[2][4][4];
    #pragma unroll
    for (int i = 0; i < 2; i++)
        #pragma unroll
        for (int j = 0; j < 4; j++)
            #pragma unroll
            for (int q = 0; q < 4; q++) acc[i][j][q] = 0.f;

    issue(0, 0);
    for (int kt = 0; kt < 4; kt++) {
        if (kt < 3) { issue((kt + 1) & 1, kt + 1); cpwait<1>(); }
        else        { cpwait<0>(); }
        __syncthreads();
        uint32_t st = sb + WBYTES + (kt & 1) * MSTAGE;
        #pragma unroll
        for (int ks = 0; ks < 2; ks++) {
            int kchunk = kt * 2 + ks;
            uint32_t awh[2][4], awl[2][4];
            #pragma unroll
            for (int i = 0; i < 2; i++) {
                int rowA = i * 16 + (lane & 15);
                uint32_t aoff = rowA * MROW + kchunk * 32 + (lane >> 4) * 16;
                ldsm_x4(awh[i], sb + aoff);
                ldsm_x4(awl[i], sb + MTERM + aoff);
            }
            int rowB = ks * 16 + (lane & 15);
            #pragma unroll
            for (int j = 0; j < 4; j++) {
                uint32_t bo = st + rowB * MROW + warp * 64 + j * 16;
                uint32_t bh[2], bl[2];
                ldsm_x2t(bh, bo);
                ldsm_x2t(bl, bo + MTERM);
                #pragma unroll
                for (int i = 0; i < 2; i++) {
                    mma16816(acc[i][j], awh[i], bh);
                    mma16816(acc[i][j], awh[i], bl);
                    mma16816(acc[i][j], awl[i], bh);
                }
            }
        }
        __syncthreads();
    }

    const int gr = lane >> 2, gc = (lane & 3) * 2;
    #pragma unroll
    for (int i = 0; i < 2; i++) {
        int o0 = i * 16 + gr;
        float bv0 = __ldg(bias + o0);
        float bv1 = __ldg(bias + o0 + 8);
        #pragma unroll
        for (int j = 0; j < 4; j++) {
            int p = n0 + warp * 32 + j * 8 + gc;
            *(float2*)(out + boff + (size_t)o0 * VL_ + p) =
                make_float2(acc[i][j][0] + bv0, acc[i][j][1] + bv0);
            *(float2*)(out + boff + (size_t)(o0 + 8) * VL_ + p) =
                make_float2(acc[i][j][2] + bv1, acc[i][j][3] + bv1);
        }
    }
}

extern "C" void kernel_launch(void* const* d_in, const int* in_sizes, int n_in,
                              void* d_out, int out_size) {
    (void)in_sizes; (void)n_in; (void)out_size;
    const float* x    = (const float*)d_in[0];
    const float* adj  = (const float*)d_in[1];
    const float* W    = (const float*)d_in[2];
    const float* bias = (const float*)d_in[3];
    float* out = (float*)d_out;

    cudaFuncSetAttribute(prop_mma, cudaFuncAttributeMaxDynamicSharedMemorySize,
                         2 * STAGE);
    cudaFuncSetAttribute(mix_mma, cudaFuncAttributeMaxDynamicSharedMemorySize,
                         MIX_SMEM);

    rowsum_kernel<<<V_, 128>>>(adj);
    buildP_kernel<<<(V_*V_)/256, 256>>>(adj);
    split_kernel<<<(int)(NELEM/4/256), 256>>>(x);

    dim3 pgrid(V_/128, B_*C_);    // (4, 512)
    prop_mma<<<pgrid, 384, 2*STAGE>>>(x, -1, 0);   // h1 = f(x)
    prop_mma<<<pgrid, 384, 2*STAGE>>>(x,  0, 1);   // h2 = f(h1)
    prop_mma<<<pgrid, 384, 2*STAGE>>>(x,  1, 2);   // h3 = f(h2)

    mix_mma<<<dim3(VL_/128, B_), 128, MIX_SMEM>>>(W, bias, out);
}

// round 4
// speedup vs baseline: 2.7537x; 1.0013x over previous
#include <cuda_runtime.h>
#include <cuda_bf16.h>
#include <cstdint>

#define B_ 16
#define C_ 32
#define V_ 512
#define L_ 168
#define VL_ (V_*L_)                      // 86016
#define CVL_ (C_*VL_)                    // 2752512
#define NELEM ((size_t)B_*C_*V_*L_)      // 44040192
#define ALPHA 0.05f
#define OMA   0.95f

// ---------------- device scratch ----------------
__device__ float g_d[V_];
__device__ __nv_bfloat16 g_Phi[V_*V_];
__device__ __nv_bfloat16 g_Plo[V_*V_];
__device__ __nv_bfloat16 g_xhi[NELEM];
__device__ __nv_bfloat16 g_xlo[NELEM];
__device__ __nv_bfloat16 g_hhi[3*NELEM];
__device__ __nv_bfloat16 g_hlo[3*NELEM];

// ---------------- PTX helpers ----------------
__device__ __forceinline__ void cpasync16(uint32_t dst, const void* src) {
    asm volatile("cp.async.cg.shared.global [%0],[%1],16;\n" :: "r"(dst), "l"(src));
}
__device__ __forceinline__ void cpcommit() { asm volatile("cp.async.commit_group;\n"); }
template<int N> __device__ __forceinline__ void cpwait() {
    asm volatile("cp.async.wait_group %0;\n" :: "n"(N));
}
__device__ __forceinline__ void ldsm_x4(uint32_t a[4], uint32_t addr) {
    asm volatile("ldmatrix.sync.aligned.m8n8.x4.shared.b16 {%0,%1,%2,%3},[%4];"
        : "=r"(a[0]), "=r"(a[1]), "=r"(a[2]), "=r"(a[3]) : "r"(addr));
}
__device__ __forceinline__ void ldsm_x2t(uint32_t b[2], uint32_t addr) {
    asm volatile("ldmatrix.sync.aligned.m8n8.x2.trans.shared.b16 {%0,%1},[%2];"
        : "=r"(b[0]), "=r"(b[1]) : "r"(addr));
}
__device__ __forceinline__ void mma16816(float c[4], const uint32_t a[4], const uint32_t b[2]) {
    asm volatile("mma.sync.aligned.m16n8k16.row.col.f32.bf16.bf16.f32 "
        "{%0,%1,%2,%3},{%4,%5,%6,%7},{%8,%9},{%0,%1,%2,%3};"
        : "+f"(c[0]), "+f"(c[1]), "+f"(c[2]), "+f"(c[3])
        : "r"(a[0]), "r"(a[1]), "r"(a[2]), "r"(a[3]), "r"(b[0]), "r"(b[1]));
}

// ---------------- adjacency prep ----------------
__global__ void rowsum_kernel(const float* __restrict__ adj) {
    int v = blockIdx.x;
    float s = 0.f;
    for (int w = threadIdx.x; w < V_; w += blockDim.x) s += adj[v*V_ + w];
    __shared__ float sh[128];
    sh[threadIdx.x] = s;
    __syncthreads();
    for (int off = 64; off > 0; off >>= 1) {
        if (threadIdx.x < off) sh[threadIdx.x] += sh[threadIdx.x + off];
        __syncthreads();
    }
    if (threadIdx.x == 0) g_d[v] = sh[0] + 1.0f;
}

__global__ void buildP_kernel(const float* __restrict__ adj) {
    int idx = blockIdx.x * blockDim.x + threadIdx.x;   // idx = w*512 + v
    int w = idx >> 9, v = idx & 511;
    float a = adj[v*V_ + w] + (v == w ? 1.f : 0.f);
    float p = a / g_d[v];
    __nv_bfloat16 hi = __float2bfloat16_rn(p);
    g_Phi[idx] = hi;
    g_Plo[idx] = __float2bfloat16_rn(p - __bfloat162float(hi));
}

__global__ void split_kernel(const float* __restrict__ x) {
    size_t i = ((size_t)blockIdx.x * 256 + threadIdx.x) * 4;
    float4 v = *(const float4*)(x + i);
    __nv_bfloat16 h0 = __float2bfloat16_rn(v.x), h1 = __float2bfloat16_rn(v.y);
    __nv_bfloat16 h2 = __float2bfloat16_rn(v.z), h3 = __float2bfloat16_rn(v.w);
    *(__nv_bfloat162*)(g_xhi + i)     = __halves2bfloat162(h0, h1);
    *(__nv_bfloat162*)(g_xhi + i + 2) = __halves2bfloat162(h2, h3);
    *(__nv_bfloat162*)(g_xlo + i)     = __halves2bfloat162(
        __float2bfloat16_rn(v.x - __bfloat162float(h0)),
        __float2bfloat16_rn(v.y - __bfloat162float(h1)));
    *(__nv_bfloat162*)(g_xlo + i + 2) = __halves2bfloat162(
        __float2bfloat16_rn(v.z - __bfloat162float(h2)),
        __float2bfloat16_rn(v.w - __bfloat162float(h3)));
}

// ---------------- tensor-core propagation ----------------
// tile BM=128 x BN=168 (full L), BK=32, 384 threads = 12 warps (4m x 3n),
// warp tile 32x56.  D = Phi*Shi + Phi*Slo + Plo*Shi; out = ALPHA*x + OMA*D,
// written only as bf16 hi/lo split.
#define A_ST   80
#define A_TERM 10240
#define B_OFF  20480   // 2*A_TERM
#define B_ROW  336     // 168 bf16
#define B_TERM 10752   // 32*336
#define STAGE  41984   // B_OFF + 2*B_TERM

__global__ __launch_bounds__(384, 1) void prop_mma(const float* __restrict__ xg,
                                                   int src_sel, int dst_sel) {
    extern __shared__ char smem[];
    uint32_t sb = (uint32_t)__cvta_generic_to_shared(smem);
    const int t = threadIdx.x;
    const int warp = t >> 5, lane = t & 31;
    const int warp_m = warp & 3, warp_n = warp >> 2;     // 4 x 3
    const int w0 = blockIdx.x * 128;
    const int bc = blockIdx.y;
    const size_t base = (size_t)bc * VL_;

    const __nv_bfloat16* __restrict__ shi =
        (src_sel < 0) ? g_xhi : (g_hhi + (size_t)src_sel * NELEM);
    const __nv_bfloat16* __restrict__ slo =
        (src_sel < 0) ? g_xlo : (g_hlo + (size_t)src_sel * NELEM);
    __nv_bfloat16* __restrict__ dhi = g_hhi + (size_t)dst_sel * NELEM;
    __nv_bfloat16* __restrict__ dlo = g_hlo + (size_t)dst_sel * NELEM;

    auto issue = [&](int s, int kt) {
        uint32_t st = sb + s * STAGE;
        #pragma unroll
        for (int i = 0; i < 3; i++) {                 // A: 1024 16B chunks
            int c = i * 384 + t;
            if (c < 1024) {
                int term = c >> 9, rem = c & 511;
                int row = rem >> 2, q = rem & 3;
                const __nv_bfloat16* src = (term ? g_Plo : g_Phi)
                    + (size_t)(w0 + row) * V_ + kt * 32 + q * 8;
                cpasync16(st + term * A_TERM + row * A_ST + q * 16, src);
            }
        }
        #pragma unroll
        for (int i = 0; i < 4; i++) {                 // B: 1344 16B chunks
            int c = i * 384 + t;
            if (c < 1344) {
                int term = c / 672, rem = c - term * 672;
                int row = rem / 21, cc = rem - row * 21;
                const __nv_bfloat16* src = (term ? slo : shi) + base
                    + (size_t)(kt * 32 + row) * L_ + cc * 8;
                cpasync16(st + B_OFF + term * B_TERM + row * B_ROW + cc * 16, src);
            }
        }
        cpcommit();
    };

    float acc[2][7][4];
    #pragma unroll
    for (int i = 0; i < 2; i++)
        #pragma unroll
        for (int j = 0; j < 7; j++)
            #pragma unroll
            for (int q = 0; q < 4; q++) acc[i][j][q] = 0.f;

    issue(0, 0);
    for (int kt = 0; kt < 16; kt++) {
        if (kt < 15) { issue((kt + 1) & 1, kt + 1); cpwait<1>(); }
        else         { cpwait<0>(); }
        __syncthreads();
        uint32_t st = sb + (kt & 1) * STAGE;
        #pragma unroll
        for (int ks = 0; ks < 2; ks++) {
            uint32_t ah[2][4], al[2][4];
            #pragma unroll
            for (int i = 0; i < 2; i++) {
                int rowA = warp_m * 32 + i * 16 + (lane & 15);
                uint32_t off = rowA * A_ST + ks * 32 + (lane >> 4) * 16;
                ldsm_x4(ah[i], st + off);
                ldsm_x4(al[i], st + A_TERM + off);
            }
            int rowB = ks * 16 + (lane & 15);
            #pragma unroll
            for (int j = 0; j < 7; j++) {
                uint32_t boff = st + B_OFF + rowB * B_ROW + warp_n * 112 + j * 16;
                uint32_t bh[2], bl[2];
                ldsm_x2t(bh, boff);
                ldsm_x2t(bl, boff + B_TERM);
                #pragma unroll
                for (int i = 0; i < 2; i++) {
                    mma16816(acc[i][j], ah[i], bh);
                    mma16816(acc[i][j], ah[i], bl);
                    mma16816(acc[i][j], al[i], bh);
                }
            }
        }
        __syncthreads();
    }

    // epilogue: o = ALPHA*x + OMA*acc -> bf16 hi/lo split only
    const int gr = lane >> 2, gc = (lane & 3) * 2;
    #pragma unroll
    for (int i = 0; i < 2; i++) {
        #pragma unroll
        for (int j = 0; j < 7; j++) {
            #pragma unroll
            for (int h = 0; h < 2; h++) {
                int wrow = w0 + warp_m * 32 + i * 16 + gr + h * 8;
                int lcol = warp_n * 56 + j * 8 + gc;
                size_t off = base + (size_t)wrow * L_ + lcol;
                float2 xv = *(const float2*)(xg + off);
                float o0 = ALPHA * xv.x + OMA * acc[i][j][2*h + 0];
                float o1 = ALPHA * xv.y + OMA * acc[i][j][2*h + 1];
                __nv_bfloat16 b0 = __float2bfloat16_rn(o0);
                __nv_bfloat16 b1 = __float2bfloat16_rn(o1);
                *(__nv_bfloat162*)(dhi + off) = __halves2bfloat162(b0, b1);
                *(__nv_bfloat162*)(dlo + off) = __halves2bfloat162(
                    __float2bfloat16_rn(o0 - __bfloat162float(b0)),
                    __float2bfloat16_rn(o1 - __bfloat162float(b1)));
            }
        }
    }
}

// ---------------- tensor-core channel mix ----------------
// out[o, b*VL+p] = bias[o] + W[o,0:128] . feat[0:128, p]
// feat rows: 0-31 x, 32-63 h1, 64-95 h2, 96-127 h3 (each as hi/lo bf16 pair)
// M=32, K=128, per-block N tile = 128. 128 thr = 4 warps along N (32 cols each).
#define MROW 272      // padded row stride bytes (128 bf16 = 256B + 16 pad)
#define MTERM 8704    // 32*272
#define WBYTES 17408  // 2 terms of W
#define MSTAGE 17408  // 2 terms of B
#define MIX_SMEM (WBYTES + 2*MSTAGE)   // 52224

__global__ __launch_bounds__(128) void mix_mma(const float* __restrict__ Wg,
                                               const float* __restrict__ bias,
                                               float* __restrict__ out) {
    extern __shared__ char smem[];
    uint32_t sb = (uint32_t)__cvta_generic_to_shared(smem);
    const int t = threadIdx.x;
    const int warp = t >> 5, lane = t & 31;
    const int n0 = blockIdx.x * 128;       // position within (v,l) plane
    const int b = blockIdx.y;
    const size_t boff = (size_t)b * CVL_;

    // W split -> smem (hi at 0, lo at MTERM)
    #pragma unroll
    for (int i = 0; i < 32; i++) {
        int idx = i * 128 + t;             // 4096 total
        int o = idx >> 7, ch = idx & 127;
        float w = Wg[idx];
        __nv_bfloat16 hi = __float2bfloat16_rn(w);
        __nv_bfloat16 lo = __float2bfloat16_rn(w - __bfloat162float(hi));
        *(__nv_bfloat16*)(smem + o * MROW + ch * 2) = hi;
        *(__nv_bfloat16*)(smem + MTERM + o * MROW + ch * 2) = lo;
    }

    const __nv_bfloat16* hitbl[4] = { g_xhi + boff, g_hhi + boff,
                                      g_hhi + NELEM + boff, g_hhi + 2*NELEM + boff };
    const __nv_bfloat16* lotbl[4] = { g_xlo + boff, g_hlo + boff,
                                      g_hlo + NELEM + boff, g_hlo + 2*NELEM + boff };

    auto issue = [&](int s, int kt) {
        uint32_t st = sb + WBYTES + s * MSTAGE;
        #pragma unroll
        for (int i = 0; i < 8; i++) {                  // 1024 chunks exactly
            int c = i * 128 + t;
            int term = c >> 9, rem = c & 511;
            int row = rem >> 4, cc = rem & 15;         // row = channel-in-slot
            const __nv_bfloat16* src = (term ? lotbl[kt] : hitbl[kt])
                + (size_t)row * VL_ + n0 + cc * 8;
            cpasync16(st + term * MTERM + row * MROW + cc * 16, src);
        }
        cpcommit();
    };

    float acc[2][4][4];
    #pragma unroll
    for (int i = 0; i < 2; i++)
        #pragma unroll
        for (int j = 0; j < 4; j++)
            #pragma unroll
            for (int q = 0; q < 4; q++) acc[i][j][q] = 0.f;

    issue(0, 0);
    for (int kt = 0; kt < 4; kt++) {
        if (kt < 3) { issue((kt + 1) & 1, kt + 1); cpwait<1>(); }
        else        { cpwait<0>(); }
        __syncthreads();
        uint32_t st = sb + WBYTES + (kt & 1) * MSTAGE;
        #pragma unroll
        for (int ks = 0; ks < 2; ks++) {
            int kchunk = kt * 2 + ks;
            uint32_t awh[2][4], awl[2][4];
            #pragma unroll
            for (int i = 0; i < 2; i++) {
                int rowA = i * 16 + (lane & 15);
                uint32_t aoff = rowA * MROW + kchunk * 32 + (lane >> 4) * 16;
                ldsm_x4(awh[i], sb + aoff);
                ldsm_x4(awl[i], sb + MTERM + aoff);
            }
            int rowB = ks * 16 + (lane & 15);
            #pragma unroll
            for (int j = 0; j < 4; j++) {
                uint32_t bo = st + rowB * MROW + warp * 64 + j * 16;
                uint32_t bh[2], bl[2];
                ldsm_x2t(bh, bo);
                ldsm_x2t(bl, bo + MTERM);
                #pragma unroll
                for (int i = 0; i < 2; i++) {
                    mma16816(acc[i][j], awh[i], bh);
                    mma16816(acc[i][j], awh[i], bl);
                    mma16816(acc[i][j], awl[i], bh);
                }
            }
        }
        __syncthreads();
    }

    const int gr = lane >> 2, gc = (lane & 3) * 2;
    #pragma unroll
    for (int i = 0; i < 2; i++) {
        int o0 = i * 16 + gr;
        float bv0 = __ldg(bias + o0);
        float bv1 = __ldg(bias + o0 + 8);
        #pragma unroll
        for (int j = 0; j < 4; j++) {
            int p = n0 + warp * 32 + j * 8 + gc;
            *(float2*)(out + boff + (size_t)o0 * VL_ + p) =
                make_float2(acc[i][j][0] + bv0, acc[i][j][1] + bv0);
            *(float2*)(out + boff + (size_t)(o0 + 8) * VL_ + p) =
                make_float2(acc[i][j][2] + bv1, acc[i][j][3] + bv1);
        }
    }
}

extern "C" void kernel_launch(void* const* d_in, const int* in_sizes, int n_in,
                              void* d_out, int out_size) {
    (void)in_sizes; (void)n_in; (void)out_size;
    const float* x    = (const float*)d_in[0];
    const float* adj  = (const float*)d_in[1];
    const float* W    = (const float*)d_in[2];
    const float* bias = (const float*)d_in[3];
    float* out = (float*)d_out;

    cudaFuncSetAttribute(prop_mma, cudaFuncAttributeMaxDynamicSharedMemorySize,
                         2 * STAGE);
    cudaFuncSetAttribute(mix_mma, cudaFuncAttributeMaxDynamicSharedMemorySize,
                         MIX_SMEM);

    rowsum_kernel<<<V_, 128>>>(adj);
    buildP_kernel<<<(V_*V_)/256, 256>>>(adj);
    split_kernel<<<(int)(NELEM/4/256), 256>>>(x);

    dim3 pgrid(V_/128, B_*C_);    // (4, 512)
    prop_mma<<<pgrid, 384, 2*STAGE>>>(x, -1, 0);   // h1 = f(x)
    prop_mma<<<pgrid, 384, 2*STAGE>>>(x,  0, 1);   // h2 = f(h1)
    prop_mma<<<pgrid, 384, 2*STAGE>>>(x,  1, 2);   // h3 = f(h2)

    mix_mma<<<dim3(VL_/128, B_), 128, MIX_SMEM>>>(W, bias, out);
}

// round 8
// speedup vs baseline: 2.7538x; 1.0000x over previous
#include <cuda_runtime.h>
#include <cuda_bf16.h>
#include <cstdint>

#define B_ 16
#define C_ 32
#define V_ 512
#define L_ 168
#define VL_ (V_*L_)                      // 86016
#define CVL_ (C_*VL_)                    // 2752512
#define NELEM ((size_t)B_*C_*V_*L_)      // 44040192
#define ALPHA 0.05f
#define OMA   0.95f

// ---------------- device scratch ----------------
__device__ float g_d[V_];
__device__ __nv_bfloat16 g_Phi[V_*V_];
__device__ __nv_bfloat16 g_Plo[V_*V_];
__device__ __nv_bfloat16 g_xhi[NELEM];
__device__ __nv_bfloat16 g_xlo[NELEM];
__device__ __nv_bfloat16 g_hhi[3*NELEM];
__device__ __nv_bfloat16 g_hlo[3*NELEM];

// ---------------- PTX helpers ----------------
__device__ __forceinline__ void cpasync16(uint32_t dst, const void* src) {
    asm volatile("cp.async.cg.shared.global [%0],[%1],16;\n" :: "r"(dst), "l"(src));
}
__device__ __forceinline__ void cpcommit() { asm volatile("cp.async.commit_group;\n"); }
template<int N> __device__ __forceinline__ void cpwait() {
    asm volatile("cp.async.wait_group %0;\n" :: "n"(N));
}
__device__ __forceinline__ void ldsm_x4(uint32_t a[4], uint32_t addr) {
    asm volatile("ldmatrix.sync.aligned.m8n8.x4.shared.b16 {%0,%1,%2,%3},[%4];"
        : "=r"(a[0]), "=r"(a[1]), "=r"(a[2]), "=r"(a[3]) : "r"(addr));
}
__device__ __forceinline__ void ldsm_x2t(uint32_t b[2], uint32_t addr) {
    asm volatile("ldmatrix.sync.aligned.m8n8.x2.trans.shared.b16 {%0,%1},[%2];"
        : "=r"(b[0]), "=r"(b[1]) : "r"(addr));
}
__device__ __forceinline__ void mma16816(float c[4], const uint32_t a[4], const uint32_t b[2]) {
    asm volatile("mma.sync.aligned.m16n8k16.row.col.f32.bf16.bf16.f32 "
        "{%0,%1,%2,%3},{%4,%5,%6,%7},{%8,%9},{%0,%1,%2,%3};"
        : "+f"(c[0]), "+f"(c[1]), "+f"(c[2]), "+f"(c[3])
        : "r"(a[0]), "r"(a[1]), "r"(a[2]), "r"(a[3]), "r"(b[0]), "r"(b[1]));
}

// ---------------- adjacency prep ----------------
__global__ void rowsum_kernel(const float* __restrict__ adj) {
    int v = blockIdx.x;
    float s = 0.f;
    for (int w = threadIdx.x; w < V_; w += blockDim.x) s += adj[v*V_ + w];
    __shared__ float sh[128];
    sh[threadIdx.x] = s;
    __syncthreads();
    for (int off = 64; off > 0; off >>= 1) {
        if (threadIdx.x < off) sh[threadIdx.x] += sh[threadIdx.x + off];
        __syncthreads();
    }
    if (threadIdx.x == 0) g_d[v] = sh[0] + 1.0f;
}

__global__ void buildP_kernel(const float* __restrict__ adj) {
    int idx = blockIdx.x * blockDim.x + threadIdx.x;   // idx = w*512 + v
    int w = idx >> 9, v = idx & 511;
    float a = adj[v*V_ + w] + (v == w ? 1.f : 0.f);
    float p = a / g_d[v];
    __nv_bfloat16 hi = __float2bfloat16_rn(p);
    g_Phi[idx] = hi;
    g_Plo[idx] = __float2bfloat16_rn(p - __bfloat162float(hi));
}

__global__ void split_kernel(const float* __restrict__ x) {
    size_t i = ((size_t)blockIdx.x * 256 + threadIdx.x) * 4;
    float4 v = *(const float4*)(x + i);
    __nv_bfloat16 h0 = __float2bfloat16_rn(v.x), h1 = __float2bfloat16_rn(v.y);
    __nv_bfloat16 h2 = __float2bfloat16_rn(v.z), h3 = __float2bfloat16_rn(v.w);
    *(__nv_bfloat162*)(g_xhi + i)     = __halves2bfloat162(h0, h1);
    *(__nv_bfloat162*)(g_xhi + i + 2) = __halves2bfloat162(h2, h3);
    *(__nv_bfloat162*)(g_xlo + i)     = __halves2bfloat162(
        __float2bfloat16_rn(v.x - __bfloat162float(h0)),
        __float2bfloat16_rn(v.y - __bfloat162float(h1)));
    *(__nv_bfloat162*)(g_xlo + i + 2) = __halves2bfloat162(
        __float2bfloat16_rn(v.z - __bfloat162float(h2)),
        __float2bfloat16_rn(v.w - __bfloat162float(h3)));
}

// ---------------- tensor-core propagation ----------------
// Tile BM=128 x BN=168, BK=32; 384 threads = 12 warps (4m x 3n), warp 32x56.
// D = Phi*Shi + Phi*Slo + Plo*Shi; out = ALPHA*x + OMA*D -> bf16 hi/lo split.
// Each CTA processes 2 consecutive bc values with a continuous 3-stage
// cp.async ring (32 k-tiles, single fill/drain; epilogue overlaps next loads).
#define A_ST   80
#define A_TERM 10240
#define B_OFF  20480   // 2*A_TERM
#define B_ROW  336     // 168 bf16
#define B_TERM 10752   // 32*336
#define STAGE  41984   // B_OFF + 2*B_TERM
#define NSTG   3
#define PROP_SMEM (NSTG*STAGE)   // 125952

__global__ __launch_bounds__(384, 1) void prop_mma(const float* __restrict__ xg,
                                                   int src_sel, int dst_sel) {
    extern __shared__ char smem[];
    uint32_t sb = (uint32_t)__cvta_generic_to_shared(smem);
    const int t = threadIdx.x;
    const int warp = t >> 5, lane = t & 31;
    const int warp_m = warp & 3, warp_n = warp >> 2;     // 4 x 3
    const int w0 = blockIdx.x * 128;
    const int bc0 = blockIdx.y * 2;

    const __nv_bfloat16* __restrict__ shi =
        (src_sel < 0) ? g_xhi : (g_hhi + (size_t)src_sel * NELEM);
    const __nv_bfloat16* __restrict__ slo =
        (src_sel < 0) ? g_xlo : (g_hlo + (size_t)src_sel * NELEM);
    __nv_bfloat16* __restrict__ dhi = g_hhi + (size_t)dst_sel * NELEM;
    __nv_bfloat16* __restrict__ dlo = g_hlo + (size_t)dst_sel * NELEM;

    // one stage = one k-tile of one bc; kk = g*16 + kt, g in {0,1}
    auto issue = [&](int slot, int kk) {
        const int g = kk >> 4, kt = kk & 15;
        const size_t base = (size_t)(bc0 + g) * VL_;
        const uint32_t st = sb + slot * STAGE;
        #pragma unroll
        for (int i = 0; i < 3; i++) {                 // A: 1024 16B chunks
            int c = i * 384 + t;
            if (c < 1024) {
                int term = c >> 9, rem = c & 511;
                int row = rem >> 2, q = rem & 3;
                const __nv_bfloat16* src = (term ? g_Plo : g_Phi)
                    + (size_t)(w0 + row) * V_ + kt * 32 + q * 8;
                cpasync16(st + term * A_TERM + row * A_ST + q * 16, src);
            }
        }
        #pragma unroll
        for (int i = 0; i < 4; i++) {                 // B: 1344 16B chunks
            int c = i * 384 + t;
            if (c < 1344) {
                int term = c / 672, rem = c - term * 672;
                int row = rem / 21, cc = rem - row * 21;
                const __nv_bfloat16* src = (term ? slo : shi) + base
                    + (size_t)(kt * 32 + row) * L_ + cc * 8;
                cpasync16(st + B_OFF + term * B_TERM + row * B_ROW + cc * 16, src);
            }
        }
        cpcommit();
    };

    float acc[2][7][4];
    #pragma unroll
    for (int i = 0; i < 2; i++)
        #pragma unroll
        for (int j = 0; j < 7; j++)
            #pragma unroll
            for (int q = 0; q < 4; q++) acc[i][j][q] = 0.f;

    issue(0, 0);
    issue(1, 1);
    for (int kk = 0; kk < 32; kk++) {
        if (kk < 30) { issue((kk + 2) % NSTG, kk + 2); cpwait<2>(); }
        else if (kk == 30) { cpwait<1>(); }
        else { cpwait<0>(); }
        __syncthreads();

        const uint32_t st = sb + (kk % NSTG) * STAGE;
        #pragma unroll
        for (int ks = 0; ks < 2; ks++) {
            uint32_t ah[2][4], al[2][4];
            #pragma unroll
            for (int i = 0; i < 2; i++) {
                int rowA = warp_m * 32 + i * 16 + (lane & 15);
                uint32_t off = rowA * A_ST + ks * 32 + (lane >> 4) * 16;
                ldsm_x4(ah[i], st + off);
                ldsm_x4(al[i], st + A_TERM + off);
            }
            int rowB = ks * 16 + (lane & 15);
            #pragma unroll
            for (int j = 0; j < 7; j++) {
                uint32_t boff = st + B_OFF + rowB * B_ROW + warp_n * 112 + j * 16;
                uint32_t bh[2], bl[2];
                ldsm_x2t(bh, boff);
                ldsm_x2t(bl, boff + B_TERM);
                #pragma unroll
                for (int i = 0; i < 2; i++) {
                    mma16816(acc[i][j], ah[i], bh);
                    mma16816(acc[i][j], ah[i], bl);
                    mma16816(acc[i][j], al[i], bh);
                }
            }
        }

        if ((kk & 15) == 15) {
            // epilogue for bc = bc0 + (kk>>4); next-bc loads are already in flight
            const size_t base = (size_t)(bc0 + (kk >> 4)) * VL_;
            const int gr = lane >> 2, gc = (lane & 3) * 2;
            #pragma unroll
            for (int i = 0; i < 2; i++) {
                #pragma unroll
                for (int j = 0; j < 7; j++) {
                    #pragma unroll
                    for (int h = 0; h < 2; h++) {
                        int wrow = w0 + warp_m * 32 + i * 16 + gr + h * 8;
                        int lcol = warp_n * 56 + j * 8 + gc;
                        size_t off = base + (size_t)wrow * L_ + lcol;
                        float2 xv = *(const float2*)(xg + off);
                        float o0 = ALPHA * xv.x + OMA * acc[i][j][2*h + 0];
                        float o1 = ALPHA * xv.y + OMA * acc[i][j][2*h + 1];
                        __nv_bfloat16 b0 = __float2bfloat16_rn(o0);
                        __nv_bfloat16 b1 = __float2bfloat16_rn(o1);
                        *(__nv_bfloat162*)(dhi + off) = __halves2bfloat162(b0, b1);
                        *(__nv_bfloat162*)(dlo + off) = __halves2bfloat162(
                            __float2bfloat16_rn(o0 - __bfloat162float(b0)),
                            __float2bfloat16_rn(o1 - __bfloat162float(b1)));
                        acc[i][j][2*h + 0] = 0.f;
                        acc[i][j][2*h + 1] = 0.f;
                    }
                }
            }
        }
        __syncthreads();
    }
}

// ---------------- tensor-core channel mix ----------------
#define MROW 272      // padded row stride bytes (128 bf16 = 256B + 16 pad)
#define MTERM 8704    // 32*272
#define WBYTES 17408  // 2 terms of W
#define MSTAGE 17408  // 2 terms of B
#define MIX_SMEM (WBYTES + 2*MSTAGE)   // 52224

__global__ __launch_bounds__(128) void mix_mma(const float* __restrict__ Wg,
                                               const float* __restrict__ bias,
                                               float* __restrict__ out) {
    extern __shared__ char smem[];
    uint32_t sb = (uint32_t)__cvta_generic_to_shared(smem);
    const int t = threadIdx.x;
    const int warp = t >> 5, lane = t & 31;
    const int n0 = blockIdx.x * 128;       // position within (v,l) plane
    const int b = blockIdx.y;
    const size_t boff = (size_t)b * CVL_;

    #pragma unroll
    for (int i = 0; i < 32; i++) {
        int idx = i * 128 + t;             // 4096 total
        int o = idx >> 7, ch = idx & 127;
        float w = Wg[idx];
        __nv_bfloat16 hi = __float2bfloat16_rn(w);
        __nv_bfloat16 lo = __float2bfloat16_rn(w - __bfloat162float(hi));
        *(__nv_bfloat16*)(smem + o * MROW + ch * 2) = hi;
        *(__nv_bfloat16*)(smem + MTERM + o * MROW + ch * 2) = lo;
    }

    const __nv_bfloat16* hitbl[4] = { g_xhi + boff, g_hhi + boff,
                                      g_hhi + NELEM + boff, g_hhi + 2*NELEM + boff };
    const __nv_bfloat16* lotbl[4] = { g_xlo + boff, g_hlo + boff,
                                      g_hlo + NELEM + boff, g_hlo + 2*NELEM + boff };

    auto issue = [&](int s, int kt) {
        uint32_t st = sb + WBYTES + s * MSTAGE;
        #pragma unroll
        for (int i = 0; i < 8; i++) {                  // 1024 chunks exactly
            int c = i * 128 + t;
            int term = c >> 9, rem = c & 511;
            int row = rem >> 4, cc = rem & 15;
            const __nv_bfloat16* src = (term ? lotbl[kt] : hitbl[kt])
                + (size_t)row * VL_ + n0 + cc * 8;
            cpasync16(st + term * MTERM + row * MROW + cc * 16, src);
        }
        cpcommit();
    };

    float acc[2][4][4];
    #pragma unroll
    for (int i = 0; i < 2; i++)
        #pragma unroll
        for (int j = 0; j < 4; j++)
            #pragma unroll
            for (int q = 0; q < 4; q++) acc[i][j][q] = 0.f;

    issue(0, 0);
    for (int kt = 0; kt < 4; kt++) {
        if (kt < 3) { issue((kt + 1) & 1, kt + 1); cpwait<1>(); }
        else        { cpwait<0>(); }
        __syncthreads();
        uint32_t st = sb + WBYTES + (kt & 1) * MSTAGE;
        #pragma unroll
        for (int ks = 0; ks < 2; ks++) {
            int kchunk = kt * 2 + ks;
            uint32_t awh[2][4], awl[2][4];
            #pragma unroll
            for (int i = 0; i < 2; i++) {
                int rowA = i * 16 + (lane & 15);
                uint32_t aoff = rowA * MROW + kchunk * 32 + (lane >> 4) * 16;
                ldsm_x4(awh[i], sb + aoff);
                ldsm_x4(awl[i], sb + MTERM + aoff);
            }
            int rowB = ks * 16 + (lane & 15);
            #pragma unroll
            for (int j = 0; j < 4; j++) {
                uint32_t bo = st + rowB * MROW + warp * 64 + j * 16;
                uint32_t bh[2], bl[2];
                ldsm_x2t(bh, bo);
                ldsm_x2t(bl, bo + MTERM);
                #pragma unroll
                for (int i = 0; i < 2; i++) {
                    mma16816(acc[i][j], awh[i], bh);
                    mma16816(acc[i][j], awh[i], bl);
                    mma16816(acc[i][j], awl[i], bh);
                }
            }
        }
        __syncthreads();
    }

    const int gr = lane >> 2, gc = (lane & 3) * 2;
    #pragma unroll
    for (int i = 0; i < 2; i++) {
        int o0 = i * 16 + gr;
        float bv0 = __ldg(bias + o0);
        float bv1 = __ldg(bias + o0 + 8);
        #pragma unroll
        for (int j = 0; j < 4; j++) {
            int p = n0 + warp * 32 + j * 8 + gc;
            *(float2*)(out + boff + (size_t)o0 * VL_ + p) =
                make_float2(acc[i][j][0] + bv0, acc[i][j][1] + bv0);
            *(float2*)(out + boff + (size_t)(o0 + 8) * VL_ + p) =
                make_float2(acc[i][j][2] + bv1, acc[i][j][3] + bv1);
        }
    }
}

extern "C" void kernel_launch(void* const* d_in, const int* in_sizes, int n_in,
                              void* d_out, int out_size) {
    (void)in_sizes; (void)n_in; (void)out_size;
    const float* x    = (const float*)d_in[0];
    const float* adj  = (const float*)d_in[1];
    const float* W    = (const float*)d_in[2];
    const float* bias = (const float*)d_in[3];
    float* out = (float*)d_out;

    cudaFuncSetAttribute(prop_mma, cudaFuncAttributeMaxDynamicSharedMemorySize,
                         PROP_SMEM);
    cudaFuncSetAttribute(mix_mma, cudaFuncAttributeMaxDynamicSharedMemorySize,
                         MIX_SMEM);

    rowsum_kernel<<<V_, 128>>>(adj);
    buildP_kernel<<<(V_*V_)/256, 256>>>(adj);
    split_kernel<<<(int)(NELEM/4/256), 256>>>(x);

    dim3 pgrid(V_/128, (B_*C_)/2);    // (4, 256) = 1024 CTAs, 2 bc each
    prop_mma<<<pgrid, 384, PROP_SMEM>>>(x, -1, 0);   // h1 = f(x)
    prop_mma<<<pgrid, 384, PROP_SMEM>>>(x,  0, 1);   // h2 = f(h1)
    prop_mma<<<pgrid, 384, PROP_SMEM>>>(x,  1, 2);   // h3 = f(h2)

    mix_mma<<<dim3(VL_/128, B_), 128, MIX_SMEM>>>(W, bias, out);
}

// round 9
// speedup vs baseline: 3.1143x; 1.1309x over previous
#include <cuda_runtime.h>
#include <cuda_bf16.h>
#include <cstdint>

#define B_ 16
#define C_ 32
#define V_ 512
#define L_ 168
#define VL_ (V_*L_)                      // 86016
#define CVL_ (C_*VL_)                    // 2752512
#define NELEM ((size_t)B_*C_*V_*L_)      // 44040192
#define ALPHA 0.05f
#define OMA   0.95f

// ---------------- device scratch ----------------
__device__ float g_d[V_];
__device__ __nv_bfloat16 g_Phi[V_*V_];
__device__ __nv_bfloat16 g_Plo[V_*V_];
__device__ __nv_bfloat16 g_xhi[NELEM];
__device__ __nv_bfloat16 g_xlo[NELEM];
__device__ __nv_bfloat16 g_hhi[3*NELEM];
__device__ __nv_bfloat16 g_hlo[3*NELEM];

// ---------------- PTX helpers ----------------
__device__ __forceinline__ void cpasync16(uint32_t dst, const void* src) {
    asm volatile("cp.async.cg.shared.global [%0],[%1],16;\n" :: "r"(dst), "l"(src));
}
__device__ __forceinline__ void cpcommit() { asm volatile("cp.async.commit_group;\n"); }
template<int N> __device__ __forceinline__ void cpwait() {
    asm volatile("cp.async.wait_group %0;\n" :: "n"(N));
}
__device__ __forceinline__ void ldsm_x4(uint32_t a[4], uint32_t addr) {
    asm volatile("ldmatrix.sync.aligned.m8n8.x4.shared.b16 {%0,%1,%2,%3},[%4];"
        : "=r"(a[0]), "=r"(a[1]), "=r"(a[2]), "=r"(a[3]) : "r"(addr));
}
__device__ __forceinline__ void ldsm_x4t(uint32_t a[4], uint32_t addr) {
    asm volatile("ldmatrix.sync.aligned.m8n8.x4.trans.shared.b16 {%0,%1,%2,%3},[%4];"
        : "=r"(a[0]), "=r"(a[1]), "=r"(a[2]), "=r"(a[3]) : "r"(addr));
}
__device__ __forceinline__ void ldsm_x2t(uint32_t b[2], uint32_t addr) {
    asm volatile("ldmatrix.sync.aligned.m8n8.x2.trans.shared.b16 {%0,%1},[%2];"
        : "=r"(b[0]), "=r"(b[1]) : "r"(addr));
}
__device__ __forceinline__ void mma16816(float c[4], const uint32_t a[4], const uint32_t b[2]) {
    asm volatile("mma.sync.aligned.m16n8k16.row.col.f32.bf16.bf16.f32 "
        "{%0,%1,%2,%3},{%4,%5,%6,%7},{%8,%9},{%0,%1,%2,%3};"
        : "+f"(c[0]), "+f"(c[1]), "+f"(c[2]), "+f"(c[3])
        : "r"(a[0]), "r"(a[1]), "r"(a[2]), "r"(a[3]), "r"(b[0]), "r"(b[1]));
}

// ---------------- adjacency prep ----------------
__global__ void rowsum_kernel(const float* __restrict__ adj) {
    int v = blockIdx.x;
    float s = 0.f;
    for (int w = threadIdx.x; w < V_; w += blockDim.x) s += adj[v*V_ + w];
    __shared__ float sh[128];
    sh[threadIdx.x] = s;
    __syncthreads();
    for (int off = 64; off > 0; off >>= 1) {
        if (threadIdx.x < off) sh[threadIdx.x] += sh[threadIdx.x + off];
        __syncthreads();
    }
    if (threadIdx.x == 0) g_d[v] = sh[0] + 1.0f;
}

__global__ void buildP_kernel(const float* __restrict__ adj) {
    int idx = blockIdx.x * blockDim.x + threadIdx.x;   // idx = w*512 + v
    int w = idx >> 9, v = idx & 511;
    float a = adj[v*V_ + w] + (v == w ? 1.f : 0.f);
    float p = a / g_d[v];
    __nv_bfloat16 hi = __float2bfloat16_rn(p);
    g_Phi[idx] = hi;
    g_Plo[idx] = __float2bfloat16_rn(p - __bfloat162float(hi));
}

__global__ void split_kernel(const float* __restrict__ x) {
    size_t i = ((size_t)blockIdx.x * 256 + threadIdx.x) * 4;
    float4 v = *(const float4*)(x + i);
    __nv_bfloat16 h0 = __float2bfloat16_rn(v.x), h1 = __float2bfloat16_rn(v.y);
    __nv_bfloat16 h2 = __float2bfloat16_rn(v.z), h3 = __float2bfloat16_rn(v.w);
    *(__nv_bfloat162*)(g_xhi + i)     = __halves2bfloat162(h0, h1);
    *(__nv_bfloat162*)(g_xhi + i + 2) = __halves2bfloat162(h2, h3);
    *(__nv_bfloat162*)(g_xlo + i)     = __halves2bfloat162(
        __float2bfloat16_rn(v.x - __bfloat162float(h0)),
        __float2bfloat16_rn(v.y - __bfloat162float(h1)));
    *(__nv_bfloat162*)(g_xlo + i + 2) = __halves2bfloat162(
        __float2bfloat16_rn(v.z - __bfloat162float(h2)),
        __float2bfloat16_rn(v.w - __bfloat162float(h3)));
}

// ---------------- tensor-core propagation ----------------
// Tile BM=64 x BN=168, BK=32; 192 threads = 6 warps (2m x 3n), warp 32x56.
// TWO CTAs per SM (launch_bounds(192,2)) -> independent scheduling domains.
// Each CTA does 2 consecutive bc with a continuous 3-stage cp.async ring.
#define A_ST   80
#define A_TERM 5120    // 64*80
#define B_OFF  10240   // 2*A_TERM
#define B_ROW  336     // 168 bf16
#define B_TERM 10752   // 32*336
#define STAGE  31744   // B_OFF + 2*B_TERM
#define NSTG   3
#define PROP_SMEM (NSTG*STAGE)   // 95232

__global__ __launch_bounds__(192, 2) void prop_mma(const float* __restrict__ xg,
                                                   int src_sel, int dst_sel) {
    extern __shared__ char smem[];
    uint32_t sb = (uint32_t)__cvta_generic_to_shared(smem);
    const int t = threadIdx.x;
    const int warp = t >> 5, lane = t & 31;
    const int warp_m = warp & 1, warp_n = warp >> 1;     // 2 x 3
    const int w0 = blockIdx.x * 64;
    const int bc0 = blockIdx.y * 2;

    const __nv_bfloat16* __restrict__ shi =
        (src_sel < 0) ? g_xhi : (g_hhi + (size_t)src_sel * NELEM);
    const __nv_bfloat16* __restrict__ slo =
        (src_sel < 0) ? g_xlo : (g_hlo + (size_t)src_sel * NELEM);
    __nv_bfloat16* __restrict__ dhi = g_hhi + (size_t)dst_sel * NELEM;
    __nv_bfloat16* __restrict__ dlo = g_hlo + (size_t)dst_sel * NELEM;

    // one stage = one k-tile of one bc; kk = g*16 + kt
    auto issue = [&](int slot, int kk) {
        const int g = kk >> 4, kt = kk & 15;
        const size_t base = (size_t)(bc0 + g) * VL_;
        const uint32_t st = sb + slot * STAGE;
        #pragma unroll
        for (int i = 0; i < 3; i++) {                 // A: 512 16B chunks
            int c = i * 192 + t;
            if (c < 512) {
                int term = c >> 8, rem = c & 255;
                int row = rem >> 2, q = rem & 3;
                const __nv_bfloat16* src = (term ? g_Plo : g_Phi)
                    + (size_t)(w0 + row) * V_ + kt * 32 + q * 8;
                cpasync16(st + term * A_TERM + row * A_ST + q * 16, src);
            }
        }
        #pragma unroll
        for (int i = 0; i < 7; i++) {                 // B: 1344 16B chunks
            int c = i * 192 + t;
            if (c < 1344) {
                int term = c / 672, rem = c - term * 672;
                int row = rem / 21, cc = rem - row * 21;
                const __nv_bfloat16* src = (term ? slo : shi) + base
                    + (size_t)(kt * 32 + row) * L_ + cc * 8;
                cpasync16(st + B_OFF + term * B_TERM + row * B_ROW + cc * 16, src);
            }
        }
        cpcommit();
    };

    float acc[2][7][4];
    #pragma unroll
    for (int i = 0; i < 2; i++)
        #pragma unroll
        for (int j = 0; j < 7; j++)
            #pragma unroll
            for (int q = 0; q < 4; q++) acc[i][j][q] = 0.f;

    issue(0, 0);
    issue(1, 1);
    for (int kk = 0; kk < 32; kk++) {
        if (kk < 30) { issue((kk + 2) % NSTG, kk + 2); cpwait<2>(); }
        else if (kk == 30) { cpwait<1>(); }
        else { cpwait<0>(); }
        __syncthreads();

        const uint32_t st = sb + (kk % NSTG) * STAGE;
        #pragma unroll
        for (int ks = 0; ks < 2; ks++) {
            // B row base for trans loads: lanes 0-15 rows k0-15 col j,
            // lanes 16-31 rows k0-15 col j+1 (x4t loads a j-pair).
            const uint32_t browb = st + B_OFF
                + (ks * 16 + (lane & 15)) * B_ROW + warp_n * 112
                + (lane >> 4) * 16;

            uint32_t bh[7][2];
            #pragma unroll
            for (int jp = 0; jp < 3; jp++) {
                uint32_t tmp[4];
                ldsm_x4t(tmp, browb + (2 * jp) * 16);
                bh[2*jp][0] = tmp[0]; bh[2*jp][1] = tmp[1];
                bh[2*jp+1][0] = tmp[2]; bh[2*jp+1][1] = tmp[3];
            }
            ldsm_x2t(bh[6], browb + 6 * 16);

            uint32_t ah[2][4], al[2][4];
            #pragma unroll
            for (int i = 0; i < 2; i++) {
                int rowA = warp_m * 32 + i * 16 + (lane & 15);
                uint32_t off = rowA * A_ST + ks * 32 + (lane >> 4) * 16;
                ldsm_x4(ah[i], st + off);
                ldsm_x4(al[i], st + A_TERM + off);
            }
            #pragma unroll
            for (int j = 0; j < 7; j++)
                #pragma unroll
                for (int i = 0; i < 2; i++) {
                    mma16816(acc[i][j], ah[i], bh[j]);
                    mma16816(acc[i][j], al[i], bh[j]);
                }

            uint32_t bl[7][2];
            #pragma unroll
            for (int jp = 0; jp < 3; jp++) {
                uint32_t tmp[4];
                ldsm_x4t(tmp, browb + B_TERM + (2 * jp) * 16);
                bl[2*jp][0] = tmp[0]; bl[2*jp][1] = tmp[1];
                bl[2*jp+1][0] = tmp[2]; bl[2*jp+1][1] = tmp[3];
            }
            ldsm_x2t(bl[6], browb + B_TERM + 6 * 16);
            #pragma unroll
            for (int j = 0; j < 7; j++)
                #pragma unroll
                for (int i = 0; i < 2; i++)
                    mma16816(acc[i][j], ah[i], bl[j]);
        }

        if ((kk & 15) == 15) {
            // epilogue for bc = bc0 + (kk>>4); next-bc loads already in flight
            const size_t base = (size_t)(bc0 + (kk >> 4)) * VL_;
            const int gr = lane >> 2, gc = (lane & 3) * 2;
            #pragma unroll
            for (int i = 0; i < 2; i++) {
                #pragma unroll
                for (int j = 0; j < 7; j++) {
                    #pragma unroll
                    for (int h = 0; h < 2; h++) {
                        int wrow = w0 + warp_m * 32 + i * 16 + gr + h * 8;
                        int lcol = warp_n * 56 + j * 8 + gc;
                        size_t off = base + (size_t)wrow * L_ + lcol;
                        float2 xv = *(const float2*)(xg + off);
                        float o0 = ALPHA * xv.x + OMA * acc[i][j][2*h + 0];
                        float o1 = ALPHA * xv.y + OMA * acc[i][j][2*h + 1];
                        __nv_bfloat16 b0 = __float2bfloat16_rn(o0);
                        __nv_bfloat16 b1 = __float2bfloat16_rn(o1);
                        *(__nv_bfloat162*)(dhi + off) = __halves2bfloat162(b0, b1);
                        *(__nv_bfloat162*)(dlo + off) = __halves2bfloat162(
                            __float2bfloat16_rn(o0 - __bfloat162float(b0)),
                            __float2bfloat16_rn(o1 - __bfloat162float(b1)));
                        acc[i][j][2*h + 0] = 0.f;
                        acc[i][j][2*h + 1] = 0.f;
                    }
                }
            }
        }
        __syncthreads();
    }
}

// ---------------- tensor-core channel mix ----------------
#define MROW 272      // padded row stride bytes (128 bf16 = 256B + 16 pad)
#define MTERM 8704    // 32*272
#define WBYTES 17408  // 2 terms of W
#define MSTAGE 17408  // 2 terms of B
#define MIX_SMEM (WBYTES + 2*MSTAGE)   // 52224

__global__ __launch_bounds__(128) void mix_mma(const float* __restrict__ Wg,
                                               const float* __restrict__ bias,
                                               float* __restrict__ out) {
    extern __shared__ char smem[];
    uint32_t sb = (uint32_t)__cvta_generic_to_shared(smem);
    const int t = threadIdx.x;
    const int warp = t >> 5, lane = t & 31;
    const int n0 = blockIdx.x * 128;       // position within (v,l) plane
    const int b = blockIdx.y;
    const size_t boff = (size_t)b * CVL_;

    #pragma unroll
    for (int i = 0; i < 32; i++) {
        int idx = i * 128 + t;             // 4096 total
        int o = idx >> 7, ch = idx & 127;
        float w = Wg[idx];
        __nv_bfloat16 hi = __float2bfloat16_rn(w);
        __nv_bfloat16 lo = __float2bfloat16_rn(w - __bfloat162float(hi));
        *(__nv_bfloat16*)(smem + o * MROW + ch * 2) = hi;
        *(__nv_bfloat16*)(smem + MTERM + o * MROW + ch * 2) = lo;
    }

    const __nv_bfloat16* hitbl[4] = { g_xhi + boff, g_hhi + boff,
                                      g_hhi + NELEM + boff, g_hhi + 2*NELEM + boff };
    const __nv_bfloat16* lotbl[4] = { g_xlo + boff, g_hlo + boff,
                                      g_hlo + NELEM + boff, g_hlo + 2*NELEM + boff };

    auto issue = [&](int s, int kt) {
        uint32_t st = sb + WBYTES + s * MSTAGE;
        #pragma unroll
        for (int i = 0; i < 8; i++) {                  // 1024 chunks exactly
            int c = i * 128 + t;
            int term = c >> 9, rem = c & 511;
            int row = rem >> 4, cc = rem & 15;
            const __nv_bfloat16* src = (term ? lotbl[kt] : hitbl[kt])
                + (size_t)row * VL_ + n0 + cc * 8;
            cpasync16(st + term * MTERM + row * MROW + cc * 16, src);
        }
        cpcommit();
    };

    float acc[2][4][4];
    #pragma unroll
    for (int i = 0; i < 2; i++)
        #pragma unroll
        for (int j = 0; j < 4; j++)
            #pragma unroll
            for (int q = 0; q < 4; q++) acc[i][j][q] = 0.f;

    issue(0, 0);
    for (int kt = 0; kt < 4; kt++) {
        if (kt < 3) { issue((kt + 1) & 1, kt + 1); cpwait<1>(); }
        else        { cpwait<0>(); }
        __syncthreads();
        uint32_t st = sb + WBYTES + (kt & 1) * MSTAGE;
        #pragma unroll
        for (int ks = 0; ks < 2; ks++) {
            int kchunk = kt * 2 + ks;
            uint32_t awh[2][4], awl[2][4];
            #pragma unroll
            for (int i = 0; i < 2; i++) {
                int rowA = i * 16 + (lane & 15);
                uint32_t aoff = rowA * MROW + kchunk * 32 + (lane >> 4) * 16;
                ldsm_x4(awh[i], sb + aoff);
                ldsm_x4(awl[i], sb + MTERM + aoff);
            }
            int rowB = ks * 16 + (lane & 15);
            #pragma unroll
            for (int j = 0; j < 4; j++) {
                uint32_t bo = st + rowB * MROW + warp * 64 + j * 16;
                uint32_t bh[2], bl[2];
                ldsm_x2t(bh, bo);
                ldsm_x2t(bl, bo + MTERM);
                #pragma unroll
                for (int i = 0; i < 2; i++) {
                    mma16816(acc[i][j], awh[i], bh);
                    mma16816(acc[i][j], awh[i], bl);
                    mma16816(acc[i][j], awl[i], bh);
                }
            }
        }
        __syncthreads();
    }

    const int gr = lane >> 2, gc = (lane & 3) * 2;
    #pragma unroll
    for (int i = 0; i < 2; i++) {
        int o0 = i * 16 + gr;
        float bv0 = __ldg(bias + o0);
        float bv1 = __ldg(bias + o0 + 8);
        #pragma unroll
        for (int j = 0; j < 4; j++) {
            int p = n0 + warp * 32 + j * 8 + gc;
            *(float2*)(out + boff + (size_t)o0 * VL_ + p) =
                make_float2(acc[i][j][0] + bv0, acc[i][j][1] + bv0);
            *(float2*)(out + boff + (size_t)(o0 + 8) * VL_ + p) =
                make_float2(acc[i][j][2] + bv1, acc[i][j][3] + bv1);
        }
    }
}

extern "C" void kernel_launch(void* const* d_in, const int* in_sizes, int n_in,
                              void* d_out, int out_size) {
    (void)in_sizes; (void)n_in; (void)out_size;
    const float* x    = (const float*)d_in[0];
    const float* adj  = (const float*)d_in[1];
    const float* W    = (const float*)d_in[2];
    const float* bias = (const float*)d_in[3];
    float* out = (float*)d_out;

    cudaFuncSetAttribute(prop_mma, cudaFuncAttributeMaxDynamicSharedMemorySize,
                         PROP_SMEM);
    cudaFuncSetAttribute(mix_mma, cudaFuncAttributeMaxDynamicSharedMemorySize,
                         MIX_SMEM);

    rowsum_kernel<<<V_, 128>>>(adj);
    buildP_kernel<<<(V_*V_)/256, 256>>>(adj);
    split_kernel<<<(int)(NELEM/4/256), 256>>>(x);

    dim3 pgrid(V_/64, (B_*C_)/2);    // (8, 256) = 2048 CTAs, 2/SM
    prop_mma<<<pgrid, 192, PROP_SMEM>>>(x, -1, 0);   // h1 = f(x)
    prop_mma<<<pgrid, 192, PROP_SMEM>>>(x,  0, 1);   // h2 = f(h1)
    prop_mma<<<pgrid, 192, PROP_SMEM>>>(x,  1, 2);   // h3 = f(h2)

    mix_mma<<<dim3(VL_/128, B_), 128, MIX_SMEM>>>(W, bias, out);
}

// round 10
// speedup vs baseline: 3.1144x; 1.0000x over previous
#include <cuda_runtime.h>
#include <cuda_bf16.h>
#include <cstdint>

#define B_ 16
#define C_ 32
#define V_ 512
#define L_ 168
#define VL_ (V_*L_)                      // 86016
#define CVL_ (C_*VL_)                    // 2752512
#define NELEM ((size_t)B_*C_*V_*L_)      // 44040192
#define ALPHA 0.05f
#define OMA   0.95f

// ---------------- device scratch ----------------
__device__ float g_d[V_];
__device__ __nv_bfloat16 g_Phi[V_*V_];
__device__ __nv_bfloat16 g_Plo[V_*V_];
__device__ __nv_bfloat16 g_xhi[NELEM];
__device__ __nv_bfloat16 g_xlo[NELEM];
__device__ __nv_bfloat16 g_hhi[3*NELEM];
__device__ __nv_bfloat16 g_hlo[3*NELEM];

// ---------------- PTX helpers ----------------
__device__ __forceinline__ void cpasync16(uint32_t dst, const void* src) {
    asm volatile("cp.async.cg.shared.global [%0],[%1],16;\n" :: "r"(dst), "l"(src));
}
__device__ __forceinline__ void cpcommit() { asm volatile("cp.async.commit_group;\n"); }
template<int N> __device__ __forceinline__ void cpwait() {
    asm volatile("cp.async.wait_group %0;\n" :: "n"(N));
}
__device__ __forceinline__ void ldsm_x4(uint32_t a[4], uint32_t addr) {
    asm volatile("ldmatrix.sync.aligned.m8n8.x4.shared.b16 {%0,%1,%2,%3},[%4];"
        : "=r"(a[0]), "=r"(a[1]), "=r"(a[2]), "=r"(a[3]) : "r"(addr));
}
__device__ __forceinline__ void ldsm_x4t(uint32_t a[4], uint32_t addr) {
    asm volatile("ldmatrix.sync.aligned.m8n8.x4.trans.shared.b16 {%0,%1,%2,%3},[%4];"
        : "=r"(a[0]), "=r"(a[1]), "=r"(a[2]), "=r"(a[3]) : "r"(addr));
}
__device__ __forceinline__ void ldsm_x2t(uint32_t b[2], uint32_t addr) {
    asm volatile("ldmatrix.sync.aligned.m8n8.x2.trans.shared.b16 {%0,%1},[%2];"
        : "=r"(b[0]), "=r"(b[1]) : "r"(addr));
}
__device__ __forceinline__ void mma16816(float c[4], const uint32_t a[4], const uint32_t b[2]) {
    asm volatile("mma.sync.aligned.m16n8k16.row.col.f32.bf16.bf16.f32 "
        "{%0,%1,%2,%3},{%4,%5,%6,%7},{%8,%9},{%0,%1,%2,%3};"
        : "+f"(c[0]), "+f"(c[1]), "+f"(c[2]), "+f"(c[3])
        : "r"(a[0]), "r"(a[1]), "r"(a[2]), "r"(a[3]), "r"(b[0]), "r"(b[1]));
}

// ---------------- adjacency prep ----------------
__global__ void rowsum_kernel(const float* __restrict__ adj) {
    int v = blockIdx.x;
    float s = 0.f;
    for (int w = threadIdx.x; w < V_; w += blockDim.x) s += adj[v*V_ + w];
    __shared__ float sh[128];
    sh[threadIdx.x] = s;
    __syncthreads();
    for (int off = 64; off > 0; off >>= 1) {
        if (threadIdx.x < off) sh[threadIdx.x] += sh[threadIdx.x + off];
        __syncthreads();
    }
    if (threadIdx.x == 0) g_d[v] = sh[0] + 1.0f;
}

__global__ void buildP_kernel(const float* __restrict__ adj) {
    int idx = blockIdx.x * blockDim.x + threadIdx.x;   // idx = w*512 + v
    int w = idx >> 9, v = idx & 511;
    float a = adj[v*V_ + w] + (v == w ? 1.f : 0.f);
    float p = a / g_d[v];
    __nv_bfloat16 hi = __float2bfloat16_rn(p);
    g_Phi[idx] = hi;
    g_Plo[idx] = __float2bfloat16_rn(p - __bfloat162float(hi));
}

__global__ void split_kernel(const float* __restrict__ x) {
    size_t i = ((size_t)blockIdx.x * 256 + threadIdx.x) * 4;
    float4 v = *(const float4*)(x + i);
    __nv_bfloat16 h0 = __float2bfloat16_rn(v.x), h1 = __float2bfloat16_rn(v.y);
    __nv_bfloat16 h2 = __float2bfloat16_rn(v.z), h3 = __float2bfloat16_rn(v.w);
    *(__nv_bfloat162*)(g_xhi + i)     = __halves2bfloat162(h0, h1);
    *(__nv_bfloat162*)(g_xhi + i + 2) = __halves2bfloat162(h2, h3);
    *(__nv_bfloat162*)(g_xlo + i)     = __halves2bfloat162(
        __float2bfloat16_rn(v.x - __bfloat162float(h0)),
        __float2bfloat16_rn(v.y - __bfloat162float(h1)));
    *(__nv_bfloat162*)(g_xlo + i + 2) = __halves2bfloat162(
        __float2bfloat16_rn(v.z - __bfloat162float(h2)),
        __float2bfloat16_rn(v.w - __bfloat162float(h3)));
}

// ---------------- tensor-core propagation ----------------
// Tile BM=64 x BN=168, BK=32; 192 threads = 6 warps (2m x 3n), warp 32x56.
// TWO CTAs per SM; each CTA does 2 consecutive bc, 3-stage cp.async ring.
// MMA schedule: term-waves (all ah*bh, all al*bh, all ah*bl) so each
// accumulator is revisited at distance 14 -> no RAW stalls.
#define A_ST   80
#define A_TERM 5120    // 64*80
#define B_OFF  10240   // 2*A_TERM
#define B_ROW  336     // 168 bf16
#define B_TERM 10752   // 32*336
#define STAGE  31744   // B_OFF + 2*B_TERM
#define NSTG   3
#define PROP_SMEM (NSTG*STAGE)   // 95232

__global__ __launch_bounds__(192, 2) void prop_mma(const float* __restrict__ xg,
                                                   int src_sel, int dst_sel) {
    extern __shared__ char smem[];
    uint32_t sb = (uint32_t)__cvta_generic_to_shared(smem);
    const int t = threadIdx.x;
    const int warp = t >> 5, lane = t & 31;
    const int warp_m = warp & 1, warp_n = warp >> 1;     // 2 x 3
    const int w0 = blockIdx.x * 64;
    const int bc0 = blockIdx.y * 2;

    const __nv_bfloat16* __restrict__ shi =
        (src_sel < 0) ? g_xhi : (g_hhi + (size_t)src_sel * NELEM);
    const __nv_bfloat16* __restrict__ slo =
        (src_sel < 0) ? g_xlo : (g_hlo + (size_t)src_sel * NELEM);
    __nv_bfloat16* __restrict__ dhi = g_hhi + (size_t)dst_sel * NELEM;
    __nv_bfloat16* __restrict__ dlo = g_hlo + (size_t)dst_sel * NELEM;

    // one stage = one k-tile of one bc; kk = g*16 + kt
    auto issue = [&](int slot, int kk) {
        const int g = kk >> 4, kt = kk & 15;
        const size_t base = (size_t)(bc0 + g) * VL_;
        const uint32_t st = sb + slot * STAGE;
        #pragma unroll
        for (int i = 0; i < 3; i++) {                 // A: 512 16B chunks
            int c = i * 192 + t;
            if (c < 512) {
                int term = c >> 8, rem = c & 255;
                int row = rem >> 2, q = rem & 3;
                const __nv_bfloat16* src = (term ? g_Plo : g_Phi)
                    + (size_t)(w0 + row) * V_ + kt * 32 + q * 8;
                cpasync16(st + term * A_TERM + row * A_ST + q * 16, src);
            }
        }
        #pragma unroll
        for (int i = 0; i < 7; i++) {                 // B: 1344 16B chunks
            int c = i * 192 + t;
            if (c < 1344) {
                int term = c / 672, rem = c - term * 672;
                int row = rem / 21, cc = rem - row * 21;
                const __nv_bfloat16* src = (term ? slo : shi) + base
                    + (size_t)(kt * 32 + row) * L_ + cc * 8;
                cpasync16(st + B_OFF + term * B_TERM + row * B_ROW + cc * 16, src);
            }
        }
        cpcommit();
    };

    float acc[2][7][4];
    #pragma unroll
    for (int i = 0; i < 2; i++)
        #pragma unroll
        for (int j = 0; j < 7; j++)
            #pragma unroll
            for (int q = 0; q < 4; q++) acc[i][j][q] = 0.f;

    issue(0, 0);
    issue(1, 1);
    for (int kk = 0; kk < 32; kk++) {
        if (kk < 30) { issue((kk + 2) % NSTG, kk + 2); cpwait<2>(); }
        else if (kk == 30) { cpwait<1>(); }
        else { cpwait<0>(); }
        __syncthreads();

        const uint32_t st = sb + (kk % NSTG) * STAGE;
        #pragma unroll
        for (int ks = 0; ks < 2; ks++) {
            const uint32_t browb = st + B_OFF
                + (ks * 16 + (lane & 15)) * B_ROW + warp_n * 112
                + (lane >> 4) * 16;

            uint32_t bh[7][2];
            #pragma unroll
            for (int jp = 0; jp < 3; jp++) {
                uint32_t tmp[4];
                ldsm_x4t(tmp, browb + (2 * jp) * 16);
                bh[2*jp][0] = tmp[0]; bh[2*jp][1] = tmp[1];
                bh[2*jp+1][0] = tmp[2]; bh[2*jp+1][1] = tmp[3];
            }
            ldsm_x2t(bh[6], browb + 6 * 16);

            uint32_t ah[2][4], al[2][4];
            #pragma unroll
            for (int i = 0; i < 2; i++) {
                int rowA = warp_m * 32 + i * 16 + (lane & 15);
                uint32_t off = rowA * A_ST + ks * 32 + (lane >> 4) * 16;
                ldsm_x4(ah[i], st + off);
                ldsm_x4(al[i], st + A_TERM + off);
            }

            // term wave 1: ah*bh (14 independent MMAs)
            #pragma unroll
            for (int j = 0; j < 7; j++)
                #pragma unroll
                for (int i = 0; i < 2; i++)
                    mma16816(acc[i][j], ah[i], bh[j]);
            // term wave 2: al*bh (acc revisit distance = 14)
            #pragma unroll
            for (int j = 0; j < 7; j++)
                #pragma unroll
                for (int i = 0; i < 2; i++)
                    mma16816(acc[i][j], al[i], bh[j]);

            uint32_t bl[7][2];
            #pragma unroll
            for (int jp = 0; jp < 3; jp++) {
                uint32_t tmp[4];
                ldsm_x4t(tmp, browb + B_TERM + (2 * jp) * 16);
                bl[2*jp][0] = tmp[0]; bl[2*jp][1] = tmp[1];
                bl[2*jp+1][0] = tmp[2]; bl[2*jp+1][1] = tmp[3];
            }
            ldsm_x2t(bl[6], browb + B_TERM + 6 * 16);
            // term wave 3: ah*bl
            #pragma unroll
            for (int j = 0; j < 7; j++)
                #pragma unroll
                for (int i = 0; i < 2; i++)
                    mma16816(acc[i][j], ah[i], bl[j]);
        }

        if ((kk & 15) == 15) {
            // epilogue for bc = bc0 + (kk>>4); next-bc loads already in flight
            const size_t base = (size_t)(bc0 + (kk >> 4)) * VL_;
            const int gr = lane >> 2, gc = (lane & 3) * 2;
            #pragma unroll
            for (int i = 0; i < 2; i++) {
                #pragma unroll
                for (int j = 0; j < 7; j++) {
                    #pragma unroll
                    for (int h = 0; h < 2; h++) {
                        int wrow = w0 + warp_m * 32 + i * 16 + gr + h * 8;
                        int lcol = warp_n * 56 + j * 8 + gc;
                        size_t off = base + (size_t)wrow * L_ + lcol;
                        float2 xv = *(const float2*)(xg + off);
                        float o0 = ALPHA * xv.x + OMA * acc[i][j][2*h + 0];
                        float o1 = ALPHA * xv.y + OMA * acc[i][j][2*h + 1];
                        __nv_bfloat16 b0 = __float2bfloat16_rn(o0);
                        __nv_bfloat16 b1 = __float2bfloat16_rn(o1);
                        *(__nv_bfloat162*)(dhi + off) = __halves2bfloat162(b0, b1);
                        *(__nv_bfloat162*)(dlo + off) = __halves2bfloat162(
                            __float2bfloat16_rn(o0 - __bfloat162float(b0)),
                            __float2bfloat16_rn(o1 - __bfloat162float(b1)));
                        acc[i][j][2*h + 0] = 0.f;
                        acc[i][j][2*h + 1] = 0.f;
                    }
                }
            }
        }
        __syncthreads();
    }
}

// ---------------- tensor-core channel mix ----------------
#define MROW 272      // padded row stride bytes (128 bf16 = 256B + 16 pad)
#define MTERM 8704    // 32*272
#define WBYTES 17408  // 2 terms of W
#define MSTAGE 17408  // 2 terms of B
#define MIX_SMEM (WBYTES + 2*MSTAGE)   // 52224

__global__ __launch_bounds__(128) void mix_mma(const float* __restrict__ Wg,
                                               const float* __restrict__ bias,
                                               float* __restrict__ out) {
    extern __shared__ char smem[];
    uint32_t sb = (uint32_t)__cvta_generic_to_shared(smem);
    const int t = threadIdx.x;
    const int warp = t >> 5, lane = t & 31;
    const int n0 = blockIdx.x * 128;       // position within (v,l) plane
    const int b = blockIdx.y;
    const size_t boff = (size_t)b * CVL_;

    #pragma unroll
    for (int i = 0; i < 32; i++) {
        int idx = i * 128 + t;             // 4096 total
        int o = idx >> 7, ch = idx & 127;
        float w = Wg[idx];
        __nv_bfloat16 hi = __float2bfloat16_rn(w);
        __nv_bfloat16 lo = __float2bfloat16_rn(w - __bfloat162float(hi));
        *(__nv_bfloat16*)(smem + o * MROW + ch * 2) = hi;
        *(__nv_bfloat16*)(smem + MTERM + o * MROW + ch * 2) = lo;
    }

    const __nv_bfloat16* hitbl[4] = { g_xhi + boff, g_hhi + boff,
                                      g_hhi + NELEM + boff, g_hhi + 2*NELEM + boff };
    const __nv_bfloat16* lotbl[4] = { g_xlo + boff, g_hlo + boff,
                                      g_hlo + NELEM + boff, g_hlo + 2*NELEM + boff };

    auto issue = [&](int s, int kt) {
        uint32_t st = sb + WBYTES + s * MSTAGE;
        #pragma unroll
        for (int i = 0; i < 8; i++) {                  // 1024 chunks exactly
            int c = i * 128 + t;
            int term = c >> 9, rem = c & 511;
            int row = rem >> 4, cc = rem & 15;
            const __nv_bfloat16* src = (term ? lotbl[kt] : hitbl[kt])
                + (size_t)row * VL_ + n0 + cc * 8;
            cpasync16(st + term * MTERM + row * MROW + cc * 16, src);
        }
        cpcommit();
    };

    float acc[2][4][4];
    #pragma unroll
    for (int i = 0; i < 2; i++)
        #pragma unroll
        for (int j = 0; j < 4; j++)
            #pragma unroll
            for (int q = 0; q < 4; q++) acc[i][j][q] = 0.f;

    issue(0, 0);
    for (int kt = 0; kt < 4; kt++) {
        if (kt < 3) { issue((kt + 1) & 1, kt + 1); cpwait<1>(); }
        else        { cpwait<0>(); }
        __syncthreads();
        uint32_t st = sb + WBYTES + (kt & 1) * MSTAGE;
        #pragma unroll
        for (int ks = 0; ks < 2; ks++) {
            int kchunk = kt * 2 + ks;
            uint32_t awh[2][4], awl[2][4];
            #pragma unroll
            for (int i = 0; i < 2; i++) {
                int rowA = i * 16 + (lane & 15);
                uint32_t aoff = rowA * MROW + kchunk * 32 + (lane >> 4) * 16;
                ldsm_x4(awh[i], sb + aoff);
                ldsm_x4(awl[i], sb + MTERM + aoff);
            }
            int rowB = ks * 16 + (lane & 15);
            uint32_t bh[4][2], bl[4][2];
            #pragma unroll
            for (int j = 0; j < 4; j++) {
                uint32_t bo = st + rowB * MROW + warp * 64 + j * 16;
                ldsm_x2t(bh[j], bo);
                ldsm_x2t(bl[j], bo + MTERM);
            }
            // term waves: acc revisit distance = 8
            #pragma unroll
            for (int j = 0; j < 4; j++)
                #pragma unroll
                for (int i = 0; i < 2; i++)
                    mma16816(acc[i][j], awh[i], bh[j]);
            #pragma unroll
            for (int j = 0; j < 4; j++)
                #pragma unroll
                for (int i = 0; i < 2; i++)
                    mma16816(acc[i][j], awh[i], bl[j]);
            #pragma unroll
            for (int j = 0; j < 4; j++)
                #pragma unroll
                for (int i = 0; i < 2; i++)
                    mma16816(acc[i][j], awl[i], bh[j]);
        }
        __syncthreads();
    }

    const int gr = lane >> 2, gc = (lane & 3) * 2;
    #pragma unroll
    for (int i = 0; i < 2; i++) {
        int o0 = i * 16 + gr;
        float bv0 = __ldg(bias + o0);
        float bv1 = __ldg(bias + o0 + 8);
        #pragma unroll
        for (int j = 0; j < 4; j++) {
            int p = n0 + warp * 32 + j * 8 + gc;
            *(float2*)(out + boff + (size_t)o0 * VL_ + p) =
                make_float2(acc[i][j][0] + bv0, acc[i][j][1] + bv0);
            *(float2*)(out + boff + (size_t)(o0 + 8) * VL_ + p) =
                make_float2(acc[i][j][2] + bv1, acc[i][j][3] + bv1);
        }
    }
}

extern "C" void kernel_launch(void* const* d_in, const int* in_sizes, int n_in,
                              void* d_out, int out_size) {
    (void)in_sizes; (void)n_in; (void)out_size;
    const float* x    = (const float*)d_in[0];
    const float* adj  = (const float*)d_in[1];
    const float* W    = (const float*)d_in[2];
    const float* bias = (const float*)d_in[3];
    float* out = (float*)d_out;

    cudaFuncSetAttribute(prop_mma, cudaFuncAttributeMaxDynamicSharedMemorySize,
                         PROP_SMEM);
    cudaFuncSetAttribute(mix_mma, cudaFuncAttributeMaxDynamicSharedMemorySize,
                         MIX_SMEM);

    rowsum_kernel<<<V_, 128>>>(adj);
    buildP_kernel<<<(V_*V_)/256, 256>>>(adj);
    split_kernel<<<(int)(NELEM/4/256), 256>>>(x);

    dim3 pgrid(V_/64, (B_*C_)/2);    // (8, 256) = 2048 CTAs, 2/SM
    prop_mma<<<pgrid, 192, PROP_SMEM>>>(x, -1, 0);   // h1 = f(x)
    prop_mma<<<pgrid, 192, PROP_SMEM>>>(x,  0, 1);   // h2 = f(h1)
    prop_mma<<<pgrid, 192, PROP_SMEM>>>(x,  1, 2);   // h3 = f(h2)

    mix_mma<<<dim3(VL_/128, B_), 128, MIX_SMEM>>>(W, bias, out);
}